// round 13
// baseline (speedup 1.0000x reference)
#include <cuda_runtime.h>
#include <cuda_fp16.h>
#include <math.h>
#include <stdint.h>

constexpr int B_  = 2;
constexpr int T_  = 2048;
constexpr int D_  = 1024;
constexpr int H_  = 16;
constexpr int HD_ = 64;
constexpr int BT_ = B_ * T_;
constexpr int D3_ = 3 * D_;
constexpr int NT_ = T_ / 128;   // 16 kv tiles

// Scratch (fp16)
__device__ __half g_q[B_ * H_ * T_ * HD_];
__device__ __half g_k[B_ * H_ * T_ * HD_];
__device__ __half g_v[B_ * H_ * T_ * HD_];
__device__ __half g_ga[BT_ * D_];                 // GEMM A (x, then attn out)
__device__ __half g_gbhi[D_ * D3_];               // GEMM B hi
__device__ __half g_gblo[D_ * D3_];               // GEMM B lo (V cols of W_qkv)

// ============================ PTX helpers ==================================
__device__ __forceinline__ uint32_t smem_u32(const void* p) {
    uint32_t a;
    asm("{ .reg .u64 t; cvta.to.shared.u64 t, %1; cvt.u32.u64 %0, t; }"
        : "=r"(a) : "l"(p));
    return a;
}
#define SWZ(o) ((uint32_t)(o) ^ ((((uint32_t)(o)) >> 3) & 0x70u))

__device__ __forceinline__ void cp16(uint32_t dst, const void* src) {
    asm volatile("cp.async.cg.shared.global [%0], [%1], 16;" :: "r"(dst), "l"(src) : "memory");
}
#define CP_COMMIT() asm volatile("cp.async.commit_group;" ::: "memory")
#define CP_WAIT0()  asm volatile("cp.async.wait_group 0;" ::: "memory")
#define CP_WAIT1()  asm volatile("cp.async.wait_group 1;" ::: "memory")

#define LDSM4(R, a) \
    asm volatile("ldmatrix.sync.aligned.m8n8.x4.shared.b16 {%0,%1,%2,%3}, [%4];" \
        : "=r"((R)[0]), "=r"((R)[1]), "=r"((R)[2]), "=r"((R)[3]) : "r"(a))
#define LDSM4T(R, a) \
    asm volatile("ldmatrix.sync.aligned.m8n8.x4.trans.shared.b16 {%0,%1,%2,%3}, [%4];" \
        : "=r"((R)[0]), "=r"((R)[1]), "=r"((R)[2]), "=r"((R)[3]) : "r"(a))

__device__ __forceinline__ void mma16816h(float* c, const uint32_t* a,
                                          uint32_t b0, uint32_t b1) {
    asm volatile("mma.sync.aligned.m16n8k16.row.col.f32.f16.f16.f32 "
        "{%0,%1,%2,%3}, {%4,%5,%6,%7}, {%8,%9}, {%0,%1,%2,%3};"
        : "+f"(c[0]), "+f"(c[1]), "+f"(c[2]), "+f"(c[3])
        : "r"(a[0]), "r"(a[1]), "r"(a[2]), "r"(a[3]), "r"(b0), "r"(b1));
}

__device__ __forceinline__ uint32_t ex2h2(uint32_t x) {
    uint32_t r;
    asm("ex2.approx.f16x2 %0, %1;" : "=r"(r) : "r"(x));
    return r;
}

__device__ __forceinline__ uint32_t packh2(float x, float y) {
    __half2 h = __floats2half2_rn(x, y);
    return *reinterpret_cast<uint32_t*>(&h);
}

// ===================== elementwise converts ================================
__global__ void tohalf_kernel(const float4* __restrict__ src,
                              uint32_t* __restrict__ dst, int n4) {
    int i = blockIdx.x * blockDim.x + threadIdx.x;
    if (i >= n4) return;
    float4 v = src[i];
    dst[2 * i]     = packh2(v.x, v.y);
    dst[2 * i + 1] = packh2(v.z, v.w);
}
__global__ void split_pair_kernel(const float4* __restrict__ src,
                                  uint32_t* __restrict__ hi,
                                  uint32_t* __restrict__ lo, int n4) {
    int i = blockIdx.x * blockDim.x + threadIdx.x;
    if (i >= n4) return;
    float4 v = src[i];
    __half h0 = __float2half_rn(v.x);
    __half h1 = __float2half_rn(v.y);
    __half h2 = __float2half_rn(v.z);
    __half h3 = __float2half_rn(v.w);
    hi[2 * i]     = (uint32_t)__half_as_ushort(h0)
                  | ((uint32_t)__half_as_ushort(h1) << 16);
    hi[2 * i + 1] = (uint32_t)__half_as_ushort(h2)
                  | ((uint32_t)__half_as_ushort(h3) << 16);
    lo[2 * i]     = packh2(v.x - __half2float(h0), v.y - __half2float(h1));
    lo[2 * i + 1] = packh2(v.z - __half2float(h2), v.w - __half2float(h3));
}

// ============ fp16 tensor-core GEMM: C = A16*(Bhi [+ Blo]) + bias ==========
// BM=128 BN=128 BK=64, 256 thr, warp m64n32.
// lo product applied only where colBase >= locol (uniform per CTA).
// mode 0: fp32 C.  mode 1: QKV epilogue (RoPE; q,k,v single fp16).
constexpr uint32_t GA_   = 0;          // 128 x 64 fp16 = 16KB
constexpr uint32_t GB_HI = 16384;
constexpr uint32_t GB_LO = 32768;
constexpr uint32_t GBUF  = 49152;
constexpr uint32_t GEMM_SMEM = 98304;
constexpr int CSTR = 132;              // staged C tile stride (floats)

__device__ __forceinline__ void gemm_load(
    uint32_t base, int tid, int rowBase, int colBase, int k0, int K, int N,
    const __half* A, const __half* Bhi, const __half* Blo, bool use_lo) {
#pragma unroll
    for (int c = tid; c < 1024; c += 256) {
        int row = c >> 3, off = c & 7;
        uint32_t sw = SWZ(row * 128 + off * 16);
        size_t g = (size_t)(rowBase + row) * K + k0 + off * 8;
        cp16(base + GA_ + sw, A + g);
    }
#pragma unroll
    for (int c = tid; c < 1024; c += 256) {
        int half = c >> 9, cc = c & 511;
        int row = cc >> 3, off = cc & 7;
        uint32_t sw = (uint32_t)(half * 8192) + SWZ(row * 128 + off * 16);
        size_t g = (size_t)(k0 + row) * N + colBase + half * 64 + off * 8;
        cp16(base + GB_HI + sw, Bhi + g);
        if (use_lo) cp16(base + GB_LO + sw, Blo + g);
    }
}

__global__ __launch_bounds__(256, 1)
void gemm_fp16_kernel(const __half* __restrict__ A,
                      const __half* __restrict__ Bhi,
                      const __half* __restrict__ Blo,
                      const float* __restrict__ bias,
                      float* __restrict__ C, int M, int N, int K,
                      int mode, int locol) {
    extern __shared__ unsigned char smraw[];
    uint32_t smem = (smem_u32(smraw) + 1023u) & ~1023u;
    unsigned char* smbase = smraw + (smem - smem_u32(smraw));

    const int tid = threadIdx.x;
    const int warp = tid >> 5, lane = tid & 31;
    const int grp = lane >> 3, rIn = lane & 7;
    const int rowBase = blockIdx.y * 128, colBase = blockIdx.x * 128;
    const bool use_lo = colBase >= locol;
    const int wrow = (warp >> 2) * 64, wc = (warp & 3) * 32;
    const int halfsel = wc >> 6;
    const int cb = (wc & 63) >> 3;
    const int NIT = K / 64;

    const uint32_t aoff = (uint32_t)((wrow + rIn + (grp & 1) * 8) * 128 + (grp >> 1) * 16);
    const uint32_t boff = (uint32_t)(grp * 1024 + rIn * 128);

    float acc[4][4][4];
#pragma unroll
    for (int m = 0; m < 4; m++)
#pragma unroll
        for (int n = 0; n < 4; n++)
#pragma unroll
            for (int i = 0; i < 4; i++) acc[m][n][i] = 0.0f;

    gemm_load(smem, tid, rowBase, colBase, 0, K, N, A, Bhi, Blo, use_lo);
    CP_COMMIT();

    for (int it = 0; it < NIT; it++) {
        __syncthreads();
        if (it + 1 < NIT) {
            gemm_load(smem + ((it + 1) & 1) * GBUF, tid, rowBase, colBase,
                      (it + 1) * 64, K, N, A, Bhi, Blo, use_lo);
            CP_COMMIT();
            CP_WAIT1();
        } else {
            CP_WAIT0();
        }
        __syncthreads();

        const uint32_t base = smem + (uint32_t)(it & 1) * GBUF;
        const uint32_t Ah = base + GA_;
        const uint32_t Bh = base + GB_HI + halfsel * 8192;
        const uint32_t Bl = base + GB_LO + halfsel * 8192;

#pragma unroll
        for (int kh = 0; kh < 2; kh++) {
            uint32_t bh[4][4], bl[4][4];
#pragma unroll
            for (int n = 0; n < 4; n++) {
                uint32_t o = boff + (uint32_t)(kh * 4096 + (cb + n) * 16);
                LDSM4T(bh[n], Bh + SWZ(o));
                if (use_lo) LDSM4T(bl[n], Bl + SWZ(o));
            }
#pragma unroll
            for (int s = 0; s < 2; s++) {
                uint32_t ah[4][4];
#pragma unroll
                for (int m = 0; m < 4; m++) {
                    uint32_t o = aoff + (uint32_t)(m * 2048 + (kh * 2 + s) * 32);
                    LDSM4(ah[m], Ah + SWZ(o));
                }
#pragma unroll
                for (int m = 0; m < 4; m++)
#pragma unroll
                    for (int n = 0; n < 4; n++) {
                        mma16816h(acc[m][n], ah[m], bh[n][2 * s], bh[n][2 * s + 1]);
                        if (use_lo)
                            mma16816h(acc[m][n], ah[m], bl[n][2 * s], bl[n][2 * s + 1]);
                    }
            }
        }
    }

    if (mode == 0) {
#pragma unroll
        for (int m = 0; m < 4; m++) {
            int r0 = rowBase + wrow + m * 16 + (lane >> 2);
#pragma unroll
            for (int n = 0; n < 4; n++) {
                int col = colBase + wc + n * 8 + 2 * (lane & 3);
                float bx = bias[col], by = bias[col + 1];
                float2 v0 = make_float2(acc[m][n][0] + bx, acc[m][n][1] + by);
                float2 v1 = make_float2(acc[m][n][2] + bx, acc[m][n][3] + by);
                *reinterpret_cast<float2*>(&C[(size_t)r0 * N + col])       = v0;
                *reinterpret_cast<float2*>(&C[(size_t)(r0 + 8) * N + col]) = v1;
            }
        }
        return;
    }

    // ---- mode 1: QKV epilogue (stage tile; RoPE; q,k,v single fp16) ----
    __syncthreads();
    float* Csm = reinterpret_cast<float*>(smbase);
#pragma unroll
    for (int m = 0; m < 4; m++) {
        int r0 = wrow + m * 16 + (lane >> 2);
#pragma unroll
        for (int n = 0; n < 4; n++) {
            int col = wc + n * 8 + 2 * (lane & 3);
            float bx = bias[colBase + col], by = bias[colBase + col + 1];
            Csm[r0 * CSTR + col]           = acc[m][n][0] + bx;
            Csm[r0 * CSTR + col + 1]       = acc[m][n][1] + by;
            Csm[(r0 + 8) * CSTR + col]     = acc[m][n][2] + bx;
            Csm[(r0 + 8) * CSTR + col + 1] = acc[m][n][3] + by;
        }
    }
    __syncthreads();

    const int type = colBase >> 10;          // 0=q, 1=k, 2=v
    const int cb2  = colBase & 1023;
    const int h0   = cb2 >> 6;               // first of 2 heads in this tile
    const int bb   = rowBase >> 11;          // batch
    const int t0   = rowBase & 2047;         // first token row

    if (type < 2) {
        __half* dst = (type == 0) ? g_q : g_k;
        int d2 = tid & 63;
        int lh = d2 >> 5, d = d2 & 31;
        float expo = (float)(2 * d) * (1.0f / (float)HD_);
        float inv  = 1.0f / powf(10000.0f, expo);
        size_t hbase = ((size_t)(bb * H_ + h0 + lh)) * T_ * HD_;
#pragma unroll 4
        for (int rr = tid >> 6; rr < 128; rr += 4) {
            int t = t0 + rr;
            float s, c;
            sincosf((float)t * inv, &s, &c);
            float v1 = Csm[rr * CSTR + lh * 64 + d];
            float v2 = Csm[rr * CSTR + lh * 64 + d + 32];
            size_t o = hbase + (size_t)t * HD_;
            dst[o + d]      = __float2half_rn(v1 * c - v2 * s);
            dst[o + d + 32] = __float2half_rn(v2 * c + v1 * s);
        }
    } else {
        int cc = tid & 127;
        int lh = cc >> 6, d = cc & 63;
        size_t hbase = ((size_t)(bb * H_ + h0 + lh)) * T_ * HD_;
#pragma unroll 4
        for (int rr = tid >> 7; rr < 128; rr += 2) {
            float v = Csm[rr * CSTR + cc];
            g_v[hbase + (size_t)(t0 + rr) * HD_ + d] = __float2half_rn(v);
        }
    }
}

// ================= mma.sync flash attention (pure fp16) ====================
// S = q16 x k16.  P = ex2.f16x2(fma(s,EXPC,bias)).  PV = p16 x v16.
// Row sums via ones-B MMA (exact same fp16 P as PV -> self-consistent).
constexpr uint32_t SM_Q  = 0;                      // 16KB
constexpr uint32_t SM_KV = 16384;                  // + buf*32768
constexpr uint32_t KV_K = 0, KV_V = 16384;
constexpr uint32_t SM_BIAS = 16384 + 2 * 32768;    // 81920; T_ floats = 8KB
constexpr uint32_t SMEM_BYTES = 81920 + 8192 + 1024;

constexpr float EXPC = 0.18033688011112042f;       // 0.125 * log2(e)
constexpr uint32_t ONES_H2 = 0x3C003C00u;          // (1.0h, 1.0h)

__device__ __forceinline__ void load_kv_tile(
    uint32_t smem, int buf, int k0, int tid,
    const __half* gk, const __half* gv) {
    uint32_t base = smem + SM_KV + (uint32_t)buf * 32768u;
#pragma unroll
    for (int c = tid; c < 1024; c += 256) {
        int row = c >> 3, off = c & 7;
        uint32_t sw = SWZ(row * 128 + off * 16);
        size_t g = (size_t)(k0 + row) * HD_ + off * 8;
        cp16(base + KV_K + sw, gk + g);
        cp16(base + KV_V + sw, gv + g);
    }
}

__global__ __launch_bounds__(256, 1)
void attn_mma_kernel(const unsigned char* __restrict__ mask) {
    extern __shared__ unsigned char smraw[];
    uint32_t smem = (smem_u32(smraw) + 1023u) & ~1023u;
    unsigned char* smbyte = smraw + (smem - smem_u32(smraw));

    const int tid  = threadIdx.x;
    const int warp = tid >> 5, lane = tid & 31;
    const int grp  = lane >> 3, rIn = lane & 7;
    const int bh = blockIdx.y, b = bh >> 4, h = bh & 15;
    const int q0 = blockIdx.x * 128;
    const int wrow = warp * 16;

    const size_t hb = (size_t)bh * T_ * HD_;
    const __half* gq = g_q + hb + (size_t)q0 * HD_;
    const __half* gk = g_k + hb;
    const __half* gv = g_v + hb;

#pragma unroll
    for (int c = tid; c < 1024; c += 256) {
        int row = c >> 3, off = c & 7;
        uint32_t sw = SWZ(row * 128 + off * 16);
        cp16(smem + SM_Q + sw, gq + (size_t)row * HD_ + off * 8);
    }
    {
        float* biasf = reinterpret_cast<float*>(smbyte + SM_BIAS);
        for (int i = tid; i < T_; i += 256)
            biasf[i] = mask[b * T_ + i] ? -200.0f : 0.0f;
    }
    load_kv_tile(smem, 0, 0, tid, gk, gv);
    CP_COMMIT();
    CP_WAIT0();
    __syncthreads();

    uint32_t qh[4][4];
    const uint32_t qoff = (uint32_t)((wrow + rIn + (grp & 1) * 8) * 128 + (grp >> 1) * 16);
#pragma unroll
    for (int kk = 0; kk < 4; kk++)
        LDSM4(qh[kk], smem + SM_Q + SWZ(qoff + kk * 32));

    float o[8][4];
#pragma unroll
    for (int j = 0; j < 8; j++)
#pragma unroll
        for (int i = 0; i < 4; i++) o[j][i] = 0.0f;
    float ls_acc[4] = {0.0f, 0.0f, 0.0f, 0.0f};   // row sums via ones-MMA

    const uint32_t kb = (uint32_t)(rIn * 128 + grp * 16);
    const uint32_t vb = (uint32_t)(grp * 1024 + rIn * 128);
    const int mcol0 = 2 * (lane & 3);
    const float* biasf = reinterpret_cast<const float*>(smbyte + SM_BIAS);

    for (int t = 0; t < NT_; t++) {
        const uint32_t kvb = smem + SM_KV + (uint32_t)(t & 1) * 32768u;

        __syncthreads();
        if (t + 1 < NT_) {
            load_kv_tile(smem, (t + 1) & 1, (t + 1) * 128, tid, gk, gv);
            CP_COMMIT();
            CP_WAIT1();
        } else {
            CP_WAIT0();
        }
        __syncthreads();

        float c[16][4];
#pragma unroll
        for (int j = 0; j < 16; j++)
#pragma unroll
            for (int i = 0; i < 4; i++) c[j][i] = 0.0f;

#pragma unroll
        for (int kp = 0; kp < 2; kp++) {
#pragma unroll
            for (int j = 0; j < 16; j++) {
                uint32_t kh[4];
                uint32_t off = (uint32_t)(1024 * j + kp * 64) + kb;
                LDSM4(kh, kvb + KV_K + SWZ(off));
                mma16816h(c[j], qh[2 * kp],     kh[0], kh[1]);
                mma16816h(c[j], qh[2 * kp + 1], kh[2], kh[3]);
            }
        }

        const float* bf = biasf + t * 128;
#pragma unroll
        for (int p = 0; p < 4; p++) {
            uint32_t ph[2][4];
#pragma unroll
            for (int q2 = 0; q2 < 2; q2++) {
#pragma unroll
                for (int jj = 0; jj < 2; jj++) {
                    int j = 4 * p + 2 * q2 + jj;
                    int cg = 8 * j + mcol0;
                    float b0 = bf[cg], b1 = bf[cg + 1];
                    float e0 = fmaf(c[j][0], EXPC, b0);
                    float e1 = fmaf(c[j][1], EXPC, b1);
                    float e2 = fmaf(c[j][2], EXPC, b0);
                    float e3 = fmaf(c[j][3], EXPC, b1);
                    ph[q2][2 * jj + 0] = ex2h2(packh2(e0, e1));
                    ph[q2][2 * jj + 1] = ex2h2(packh2(e2, e3));
                }
                // row sums on tensor core: B = ones
                mma16816h(ls_acc, ph[q2], ONES_H2, ONES_H2);
            }
#pragma unroll
            for (int jh = 0; jh < 8; jh++) {
                uint32_t vh[4];
                uint32_t off = (uint32_t)(4096 * p + 16 * jh) + vb;
                LDSM4T(vh, kvb + KV_V + SWZ(off));
                mma16816h(o[jh], ph[0], vh[0], vh[1]);
                mma16816h(o[jh], ph[1], vh[2], vh[3]);
            }
        }
    }

    // ls_acc: all 8 output columns hold the same row sum; no shuffles needed
    float i0 = 1.0f / ls_acc[0];
    float i1 = 1.0f / ls_acc[2];

    // epilogue: write fp16 O directly into out-proj A operand
    int r = q0 + wrow + (lane >> 2);
    size_t off0 = ((size_t)(b * T_ + r) * D_ + h * HD_ + mcol0) >> 1;  // u32 index
    uint32_t* ga = reinterpret_cast<uint32_t*>(g_ga);
#pragma unroll
    for (int jh = 0; jh < 8; jh++) {
        size_t i_w = off0 + 4 * jh;
        ga[i_w]          = packh2(o[jh][0] * i0, o[jh][1] * i0);
        ga[i_w + 4 * D_] = packh2(o[jh][2] * i1, o[jh][3] * i1);   // row r+8
    }
}

// ============================== Launch =====================================
extern "C" void kernel_launch(void* const* d_in, const int* in_sizes, int n_in,
                              void* d_out, int out_size) {
    const float* x     = (const float*)d_in[0];
    const float* W_qkv = (const float*)d_in[1];
    const float* b_qkv = (const float*)d_in[2];
    const float* W_out = (const float*)d_in[3];
    const float* b_out = (const float*)d_in[4];
    const unsigned char* pmask = (const unsigned char*)d_in[5];
    float* out = (float*)d_out;

    __half *ga, *bhi, *blo;
    cudaGetSymbolAddress((void**)&ga,  g_ga);
    cudaGetSymbolAddress((void**)&bhi, g_gbhi);
    cudaGetSymbolAddress((void**)&blo, g_gblo);

    cudaFuncSetAttribute(gemm_fp16_kernel,
                         cudaFuncAttributeMaxDynamicSharedMemorySize, (int)GEMM_SMEM);
    cudaFuncSetAttribute(attn_mma_kernel,
                         cudaFuncAttributeMaxDynamicSharedMemorySize, (int)SMEM_BYTES);

    // 1) x -> fp16; W_qkv -> fp16 split; fused QKV GEMM + RoPE epilogue.
    //    lo product only for V column-tiles (colBase >= 2048).
    tohalf_kernel<<<(BT_ * D_ / 4) / 256, 256>>>(
        (const float4*)x, (uint32_t*)ga, BT_ * D_ / 4);
    split_pair_kernel<<<(D_ * D3_ / 4) / 256, 256>>>(
        (const float4*)W_qkv, (uint32_t*)bhi, (uint32_t*)blo, D_ * D3_ / 4);
    gemm_fp16_kernel<<<dim3(D3_ / 128, BT_ / 128), 256, GEMM_SMEM>>>(
        ga, bhi, blo, b_qkv, nullptr, BT_, D3_, D_, 1, 2048);

    // 2) flash attention (pure fp16; writes out-proj A operand)
    attn_mma_kernel<<<dim3(T_ / 128, B_ * H_), 256, SMEM_BYTES>>>(pmask);

    // 3) W_out -> fp16 (single); out-proj GEMM (1 product) -> d_out
    tohalf_kernel<<<(D_ * D_ / 4) / 256, 256>>>(
        (const float4*)W_out, (uint32_t*)bhi, D_ * D_ / 4);
    gemm_fp16_kernel<<<dim3(D_ / 128, BT_ / 128), 256, GEMM_SMEM>>>(
        ga, bhi, nullptr, b_out, out, BT_, D_, D_, 0, 1 << 30);
}

// round 14
// speedup vs baseline: 1.0343x; 1.0343x over previous
#include <cuda_runtime.h>
#include <cuda_fp16.h>
#include <math.h>
#include <stdint.h>

constexpr int B_  = 2;
constexpr int T_  = 2048;
constexpr int D_  = 1024;
constexpr int H_  = 16;
constexpr int HD_ = 64;
constexpr int BT_ = B_ * T_;
constexpr int D3_ = 3 * D_;
constexpr int NT_ = T_ / 128;   // 16 kv tiles

// Scratch (fp16)
__device__ __half g_q[B_ * H_ * T_ * HD_];
__device__ __half g_k[B_ * H_ * T_ * HD_];
__device__ __half g_v[B_ * H_ * T_ * HD_];
__device__ __half g_ga[BT_ * D_];                 // GEMM A (x, then attn out)
__device__ __half g_gbhi[D_ * D3_];               // GEMM B hi
__device__ __half g_gblo[D_ * D3_];               // GEMM B lo (W_qkv)

// ============================ PTX helpers ==================================
__device__ __forceinline__ uint32_t smem_u32(const void* p) {
    uint32_t a;
    asm("{ .reg .u64 t; cvta.to.shared.u64 t, %1; cvt.u32.u64 %0, t; }"
        : "=r"(a) : "l"(p));
    return a;
}
#define SWZ(o) ((uint32_t)(o) ^ ((((uint32_t)(o)) >> 3) & 0x70u))

__device__ __forceinline__ void cp16(uint32_t dst, const void* src) {
    asm volatile("cp.async.cg.shared.global [%0], [%1], 16;" :: "r"(dst), "l"(src) : "memory");
}
#define CP_COMMIT() asm volatile("cp.async.commit_group;" ::: "memory")
#define CP_WAIT0()  asm volatile("cp.async.wait_group 0;" ::: "memory")
#define CP_WAIT1()  asm volatile("cp.async.wait_group 1;" ::: "memory")

#define LDSM4(R, a) \
    asm volatile("ldmatrix.sync.aligned.m8n8.x4.shared.b16 {%0,%1,%2,%3}, [%4];" \
        : "=r"((R)[0]), "=r"((R)[1]), "=r"((R)[2]), "=r"((R)[3]) : "r"(a))
#define LDSM4T(R, a) \
    asm volatile("ldmatrix.sync.aligned.m8n8.x4.trans.shared.b16 {%0,%1,%2,%3}, [%4];" \
        : "=r"((R)[0]), "=r"((R)[1]), "=r"((R)[2]), "=r"((R)[3]) : "r"(a))

__device__ __forceinline__ void mma16816h(float* c, const uint32_t* a,
                                          uint32_t b0, uint32_t b1) {
    asm volatile("mma.sync.aligned.m16n8k16.row.col.f32.f16.f16.f32 "
        "{%0,%1,%2,%3}, {%4,%5,%6,%7}, {%8,%9}, {%0,%1,%2,%3};"
        : "+f"(c[0]), "+f"(c[1]), "+f"(c[2]), "+f"(c[3])
        : "r"(a[0]), "r"(a[1]), "r"(a[2]), "r"(a[3]), "r"(b0), "r"(b1));
}

__device__ __forceinline__ uint32_t ex2h2(uint32_t x) {
    uint32_t r;
    asm("ex2.approx.f16x2 %0, %1;" : "=r"(r) : "r"(x));
    return r;
}

__device__ __forceinline__ uint32_t packh2(float x, float y) {
    __half2 h = __floats2half2_rn(x, y);
    return *reinterpret_cast<uint32_t*>(&h);
}

// ===================== elementwise converts ================================
__global__ void tohalf_kernel(const float4* __restrict__ src,
                              uint32_t* __restrict__ dst, int n4) {
    int i = blockIdx.x * blockDim.x + threadIdx.x;
    if (i >= n4) return;
    float4 v = src[i];
    dst[2 * i]     = packh2(v.x, v.y);
    dst[2 * i + 1] = packh2(v.z, v.w);
}
__global__ void split_pair_kernel(const float4* __restrict__ src,
                                  uint32_t* __restrict__ hi,
                                  uint32_t* __restrict__ lo, int n4) {
    int i = blockIdx.x * blockDim.x + threadIdx.x;
    if (i >= n4) return;
    float4 v = src[i];
    __half h0 = __float2half_rn(v.x);
    __half h1 = __float2half_rn(v.y);
    __half h2 = __float2half_rn(v.z);
    __half h3 = __float2half_rn(v.w);
    hi[2 * i]     = (uint32_t)__half_as_ushort(h0)
                  | ((uint32_t)__half_as_ushort(h1) << 16);
    hi[2 * i + 1] = (uint32_t)__half_as_ushort(h2)
                  | ((uint32_t)__half_as_ushort(h3) << 16);
    lo[2 * i]     = packh2(v.x - __half2float(h0), v.y - __half2float(h1));
    lo[2 * i + 1] = packh2(v.z - __half2float(h2), v.w - __half2float(h3));
}

// ============ fp16 tensor-core GEMM: C = A16 * (Bhi [+ Blo]) + bias ========
// BM=128 BN=128 BK=64, 256 thr, warp m64n32. PRODS = 1 or 2 (template).
// mode 0: fp32 C.  mode 1: QKV epilogue (RoPE; q,k,v single fp16).
constexpr uint32_t GA_   = 0;          // 128 x 64 fp16 = 16KB
constexpr uint32_t GB_HI = 16384;
constexpr uint32_t GB_LO = 32768;
constexpr uint32_t GBUF  = 49152;
constexpr uint32_t GEMM_SMEM = 98304;
constexpr int CSTR = 132;              // staged C tile stride (floats)

template<int PRODS>
__device__ __forceinline__ void gemm_load(
    uint32_t base, int tid, int rowBase, int colBase, int k0, int K, int N,
    const __half* A, const __half* Bhi, const __half* Blo) {
#pragma unroll
    for (int c = tid; c < 1024; c += 256) {
        int row = c >> 3, off = c & 7;
        uint32_t sw = SWZ(row * 128 + off * 16);
        size_t g = (size_t)(rowBase + row) * K + k0 + off * 8;
        cp16(base + GA_ + sw, A + g);
    }
#pragma unroll
    for (int c = tid; c < 1024; c += 256) {
        int half = c >> 9, cc = c & 511;
        int row = cc >> 3, off = cc & 7;
        uint32_t sw = (uint32_t)(half * 8192) + SWZ(row * 128 + off * 16);
        size_t g = (size_t)(k0 + row) * N + colBase + half * 64 + off * 8;
        cp16(base + GB_HI + sw, Bhi + g);
        if (PRODS == 2) cp16(base + GB_LO + sw, Blo + g);
    }
}

template<int PRODS>
__global__ __launch_bounds__(256, 1)
void gemm_fp16_kernel(const __half* __restrict__ A,
                      const __half* __restrict__ Bhi,
                      const __half* __restrict__ Blo,
                      const float* __restrict__ bias,
                      float* __restrict__ C, int M, int N, int K, int mode) {
    extern __shared__ unsigned char smraw[];
    uint32_t smem = (smem_u32(smraw) + 1023u) & ~1023u;
    unsigned char* smbase = smraw + (smem - smem_u32(smraw));

    const int tid = threadIdx.x;
    const int warp = tid >> 5, lane = tid & 31;
    const int grp = lane >> 3, rIn = lane & 7;
    const int rowBase = blockIdx.y * 128, colBase = blockIdx.x * 128;
    const int wrow = (warp >> 2) * 64, wc = (warp & 3) * 32;
    const int halfsel = wc >> 6;
    const int cb = (wc & 63) >> 3;
    const int NIT = K / 64;

    const uint32_t aoff = (uint32_t)((wrow + rIn + (grp & 1) * 8) * 128 + (grp >> 1) * 16);
    const uint32_t boff = (uint32_t)(grp * 1024 + rIn * 128);

    float acc[4][4][4];
#pragma unroll
    for (int m = 0; m < 4; m++)
#pragma unroll
        for (int n = 0; n < 4; n++)
#pragma unroll
            for (int i = 0; i < 4; i++) acc[m][n][i] = 0.0f;

    gemm_load<PRODS>(smem, tid, rowBase, colBase, 0, K, N, A, Bhi, Blo);
    CP_COMMIT();

    for (int it = 0; it < NIT; it++) {
        __syncthreads();
        if (it + 1 < NIT) {
            gemm_load<PRODS>(smem + ((it + 1) & 1) * GBUF, tid, rowBase, colBase,
                             (it + 1) * 64, K, N, A, Bhi, Blo);
            CP_COMMIT();
            CP_WAIT1();
        } else {
            CP_WAIT0();
        }
        __syncthreads();

        const uint32_t base = smem + (uint32_t)(it & 1) * GBUF;
        const uint32_t Ah = base + GA_;
        const uint32_t Bh = base + GB_HI + halfsel * 8192;
        const uint32_t Bl = base + GB_LO + halfsel * 8192;

#pragma unroll
        for (int kh = 0; kh < 2; kh++) {
            uint32_t bh[4][4], bl[4][4];
#pragma unroll
            for (int n = 0; n < 4; n++) {
                uint32_t o = boff + (uint32_t)(kh * 4096 + (cb + n) * 16);
                LDSM4T(bh[n], Bh + SWZ(o));
                if (PRODS == 2) LDSM4T(bl[n], Bl + SWZ(o));
            }
#pragma unroll
            for (int s = 0; s < 2; s++) {
                uint32_t ah[4][4];
#pragma unroll
                for (int m = 0; m < 4; m++) {
                    uint32_t o = aoff + (uint32_t)(m * 2048 + (kh * 2 + s) * 32);
                    LDSM4(ah[m], Ah + SWZ(o));
                }
#pragma unroll
                for (int m = 0; m < 4; m++)
#pragma unroll
                    for (int n = 0; n < 4; n++) {
                        mma16816h(acc[m][n], ah[m], bh[n][2 * s], bh[n][2 * s + 1]);
                        if (PRODS == 2)
                            mma16816h(acc[m][n], ah[m], bl[n][2 * s], bl[n][2 * s + 1]);
                    }
            }
        }
    }

    if (mode == 0) {
#pragma unroll
        for (int m = 0; m < 4; m++) {
            int r0 = rowBase + wrow + m * 16 + (lane >> 2);
#pragma unroll
            for (int n = 0; n < 4; n++) {
                int col = colBase + wc + n * 8 + 2 * (lane & 3);
                float bx = bias[col], by = bias[col + 1];
                float2 v0 = make_float2(acc[m][n][0] + bx, acc[m][n][1] + by);
                float2 v1 = make_float2(acc[m][n][2] + bx, acc[m][n][3] + by);
                *reinterpret_cast<float2*>(&C[(size_t)r0 * N + col])       = v0;
                *reinterpret_cast<float2*>(&C[(size_t)(r0 + 8) * N + col]) = v1;
            }
        }
        return;
    }

    // ---- mode 1: QKV epilogue (stage tile; RoPE; q,k,v single fp16) ----
    __syncthreads();
    float* Csm = reinterpret_cast<float*>(smbase);
#pragma unroll
    for (int m = 0; m < 4; m++) {
        int r0 = wrow + m * 16 + (lane >> 2);
#pragma unroll
        for (int n = 0; n < 4; n++) {
            int col = wc + n * 8 + 2 * (lane & 3);
            float bx = bias[colBase + col], by = bias[colBase + col + 1];
            Csm[r0 * CSTR + col]           = acc[m][n][0] + bx;
            Csm[r0 * CSTR + col + 1]       = acc[m][n][1] + by;
            Csm[(r0 + 8) * CSTR + col]     = acc[m][n][2] + bx;
            Csm[(r0 + 8) * CSTR + col + 1] = acc[m][n][3] + by;
        }
    }
    __syncthreads();

    const int type = colBase >> 10;          // 0=q, 1=k, 2=v
    const int cb2  = colBase & 1023;
    const int h0   = cb2 >> 6;               // first of 2 heads in this tile
    const int bb   = rowBase >> 11;          // batch
    const int t0   = rowBase & 2047;         // first token row

    if (type < 2) {
        __half* dst = (type == 0) ? g_q : g_k;
        int d2 = tid & 63;                   // pair-column within 2 heads
        int lh = d2 >> 5, d = d2 & 31;
        float expo = (float)(2 * d) * (1.0f / (float)HD_);
        float inv  = 1.0f / powf(10000.0f, expo);
        size_t hbase = ((size_t)(bb * H_ + h0 + lh)) * T_ * HD_;
#pragma unroll 4
        for (int rr = tid >> 6; rr < 128; rr += 4) {
            int t = t0 + rr;
            float s, c;
            sincosf((float)t * inv, &s, &c);
            float v1 = Csm[rr * CSTR + lh * 64 + d];
            float v2 = Csm[rr * CSTR + lh * 64 + d + 32];
            size_t o = hbase + (size_t)t * HD_;
            dst[o + d]      = __float2half_rn(v1 * c - v2 * s);
            dst[o + d + 32] = __float2half_rn(v2 * c + v1 * s);
        }
    } else {
        int cc = tid & 127;
        int lh = cc >> 6, d = cc & 63;
        size_t hbase = ((size_t)(bb * H_ + h0 + lh)) * T_ * HD_;
#pragma unroll 4
        for (int rr = tid >> 7; rr < 128; rr += 2) {
            float v = Csm[rr * CSTR + cc];
            g_v[hbase + (size_t)(t0 + rr) * HD_ + d] = __float2half_rn(v);
        }
    }
}

// ================= mma.sync flash attention (pure fp16) ====================
// S = q16 x k16.  P = ex2.f16x2(fma(s,EXPC,bias)).  PV = p16 x v16.
// Row sums via ones-B MMA (same fp16 P as PV -> self-consistent).
constexpr uint32_t SM_Q  = 0;                      // 16KB
constexpr uint32_t SM_KV = 16384;                  // + buf*32768
constexpr uint32_t KV_K = 0, KV_V = 16384;
constexpr uint32_t SM_BIAS = 16384 + 2 * 32768;    // 81920; T_ floats = 8KB
constexpr uint32_t SMEM_BYTES = 81920 + 8192 + 1024;

constexpr float EXPC = 0.18033688011112042f;       // 0.125 * log2(e)
constexpr uint32_t ONES_H2 = 0x3C003C00u;          // (1.0h, 1.0h)

__device__ __forceinline__ void load_kv_tile(
    uint32_t smem, int buf, int k0, int tid,
    const __half* gk, const __half* gv) {
    uint32_t base = smem + SM_KV + (uint32_t)buf * 32768u;
#pragma unroll
    for (int c = tid; c < 1024; c += 256) {
        int row = c >> 3, off = c & 7;
        uint32_t sw = SWZ(row * 128 + off * 16);
        size_t g = (size_t)(k0 + row) * HD_ + off * 8;
        cp16(base + KV_K + sw, gk + g);
        cp16(base + KV_V + sw, gv + g);
    }
}

__global__ __launch_bounds__(256, 1)
void attn_mma_kernel(const unsigned char* __restrict__ mask) {
    extern __shared__ unsigned char smraw[];
    uint32_t smem = (smem_u32(smraw) + 1023u) & ~1023u;
    unsigned char* smbyte = smraw + (smem - smem_u32(smraw));

    const int tid  = threadIdx.x;
    const int warp = tid >> 5, lane = tid & 31;
    const int grp  = lane >> 3, rIn = lane & 7;
    const int bh = blockIdx.y, b = bh >> 4, h = bh & 15;
    const int q0 = blockIdx.x * 128;
    const int wrow = warp * 16;

    const size_t hb = (size_t)bh * T_ * HD_;
    const __half* gq = g_q + hb + (size_t)q0 * HD_;
    const __half* gk = g_k + hb;
    const __half* gv = g_v + hb;

#pragma unroll
    for (int c = tid; c < 1024; c += 256) {
        int row = c >> 3, off = c & 7;
        uint32_t sw = SWZ(row * 128 + off * 16);
        cp16(smem + SM_Q + sw, gq + (size_t)row * HD_ + off * 8);
    }
    {
        float* biasf = reinterpret_cast<float*>(smbyte + SM_BIAS);
        for (int i = tid; i < T_; i += 256)
            biasf[i] = mask[b * T_ + i] ? -200.0f : 0.0f;
    }
    load_kv_tile(smem, 0, 0, tid, gk, gv);
    CP_COMMIT();
    CP_WAIT0();
    __syncthreads();

    uint32_t qh[4][4];
    const uint32_t qoff = (uint32_t)((wrow + rIn + (grp & 1) * 8) * 128 + (grp >> 1) * 16);
#pragma unroll
    for (int kk = 0; kk < 4; kk++)
        LDSM4(qh[kk], smem + SM_Q + SWZ(qoff + kk * 32));

    float o[8][4];
#pragma unroll
    for (int j = 0; j < 8; j++)
#pragma unroll
        for (int i = 0; i < 4; i++) o[j][i] = 0.0f;
    float ls_acc[4] = {0.0f, 0.0f, 0.0f, 0.0f};   // row sums via ones-MMA

    const uint32_t kb = (uint32_t)(rIn * 128 + grp * 16);
    const uint32_t vb = (uint32_t)(grp * 1024 + rIn * 128);
    const int mcol0 = 2 * (lane & 3);
    const float* biasf = reinterpret_cast<const float*>(smbyte + SM_BIAS);

    for (int t = 0; t < NT_; t++) {
        const uint32_t kvb = smem + SM_KV + (uint32_t)(t & 1) * 32768u;

        __syncthreads();
        if (t + 1 < NT_) {
            load_kv_tile(smem, (t + 1) & 1, (t + 1) * 128, tid, gk, gv);
            CP_COMMIT();
            CP_WAIT1();
        } else {
            CP_WAIT0();
        }
        __syncthreads();

        float c[16][4];
#pragma unroll
        for (int j = 0; j < 16; j++)
#pragma unroll
            for (int i = 0; i < 4; i++) c[j][i] = 0.0f;

#pragma unroll
        for (int kp = 0; kp < 2; kp++) {
#pragma unroll
            for (int j = 0; j < 16; j++) {
                uint32_t kh[4];
                uint32_t off = (uint32_t)(1024 * j + kp * 64) + kb;
                LDSM4(kh, kvb + KV_K + SWZ(off));
                mma16816h(c[j], qh[2 * kp],     kh[0], kh[1]);
                mma16816h(c[j], qh[2 * kp + 1], kh[2], kh[3]);
            }
        }

        const float* bf = biasf + t * 128;
#pragma unroll
        for (int p = 0; p < 4; p++) {
            uint32_t ph[2][4];
#pragma unroll
            for (int q2 = 0; q2 < 2; q2++) {
#pragma unroll
                for (int jj = 0; jj < 2; jj++) {
                    int j = 4 * p + 2 * q2 + jj;
                    int cg = 8 * j + mcol0;
                    float b0 = bf[cg], b1 = bf[cg + 1];
                    float e0 = fmaf(c[j][0], EXPC, b0);
                    float e1 = fmaf(c[j][1], EXPC, b1);
                    float e2 = fmaf(c[j][2], EXPC, b0);
                    float e3 = fmaf(c[j][3], EXPC, b1);
                    ph[q2][2 * jj + 0] = ex2h2(packh2(e0, e1));
                    ph[q2][2 * jj + 1] = ex2h2(packh2(e2, e3));
                }
                // row sums on tensor core: B = ones
                mma16816h(ls_acc, ph[q2], ONES_H2, ONES_H2);
            }
#pragma unroll
            for (int jh = 0; jh < 8; jh++) {
                uint32_t vh[4];
                uint32_t off = (uint32_t)(4096 * p + 16 * jh) + vb;
                LDSM4T(vh, kvb + KV_V + SWZ(off));
                mma16816h(o[jh], ph[0], vh[0], vh[1]);
                mma16816h(o[jh], ph[1], vh[2], vh[3]);
            }
        }
    }

    float i0 = 1.0f / ls_acc[0];
    float i1 = 1.0f / ls_acc[2];

    // epilogue: write fp16 O directly into out-proj A operand
    int r = q0 + wrow + (lane >> 2);
    size_t off0 = ((size_t)(b * T_ + r) * D_ + h * HD_ + mcol0) >> 1;  // u32 index
    uint32_t* ga = reinterpret_cast<uint32_t*>(g_ga);
#pragma unroll
    for (int jh = 0; jh < 8; jh++) {
        size_t i_w = off0 + 4 * jh;
        ga[i_w]          = packh2(o[jh][0] * i0, o[jh][1] * i0);
        ga[i_w + 4 * D_] = packh2(o[jh][2] * i1, o[jh][3] * i1);   // row r+8
    }
}

// ============================== Launch =====================================
extern "C" void kernel_launch(void* const* d_in, const int* in_sizes, int n_in,
                              void* d_out, int out_size) {
    const float* x     = (const float*)d_in[0];
    const float* W_qkv = (const float*)d_in[1];
    const float* b_qkv = (const float*)d_in[2];
    const float* W_out = (const float*)d_in[3];
    const float* b_out = (const float*)d_in[4];
    const unsigned char* pmask = (const unsigned char*)d_in[5];
    float* out = (float*)d_out;

    __half *ga, *bhi, *blo;
    cudaGetSymbolAddress((void**)&ga,  g_ga);
    cudaGetSymbolAddress((void**)&bhi, g_gbhi);
    cudaGetSymbolAddress((void**)&blo, g_gblo);

    cudaFuncSetAttribute(gemm_fp16_kernel<2>,
                         cudaFuncAttributeMaxDynamicSharedMemorySize, (int)GEMM_SMEM);
    cudaFuncSetAttribute(gemm_fp16_kernel<1>,
                         cudaFuncAttributeMaxDynamicSharedMemorySize, (int)GEMM_SMEM);
    cudaFuncSetAttribute(attn_mma_kernel,
                         cudaFuncAttributeMaxDynamicSharedMemorySize, (int)SMEM_BYTES);

    // 1) x -> fp16; W_qkv -> fp16 split; fused QKV GEMM (2 prod) + RoPE epilogue
    tohalf_kernel<<<(BT_ * D_ / 4) / 256, 256>>>(
        (const float4*)x, (uint32_t*)ga, BT_ * D_ / 4);
    split_pair_kernel<<<(D_ * D3_ / 4) / 256, 256>>>(
        (const float4*)W_qkv, (uint32_t*)bhi, (uint32_t*)blo, D_ * D3_ / 4);
    gemm_fp16_kernel<2><<<dim3(D3_ / 128, BT_ / 128), 256, GEMM_SMEM>>>(
        ga, bhi, blo, b_qkv, nullptr, BT_, D3_, D_, 1);

    // 2) flash attention (pure fp16; writes out-proj A operand)
    attn_mma_kernel<<<dim3(T_ / 128, B_ * H_), 256, SMEM_BYTES>>>(pmask);

    // 3) W_out -> fp16 (single); out-proj GEMM (1 prod) -> d_out
    tohalf_kernel<<<(D_ * D_ / 4) / 256, 256>>>(
        (const float4*)W_out, (uint32_t*)bhi, D_ * D_ / 4);
    gemm_fp16_kernel<1><<<dim3(D_ / 128, BT_ / 128), 256, GEMM_SMEM>>>(
        ga, bhi, nullptr, b_out, out, BT_, D_, D_, 0);
}

// round 15
// speedup vs baseline: 1.0541x; 1.0192x over previous
#include <cuda_runtime.h>
#include <cuda_fp16.h>
#include <math.h>
#include <stdint.h>

constexpr int B_  = 2;
constexpr int T_  = 2048;
constexpr int D_  = 1024;
constexpr int H_  = 16;
constexpr int HD_ = 64;
constexpr int BT_ = B_ * T_;
constexpr int D3_ = 3 * D_;
constexpr int NT_ = T_ / 128;   // 16 kv tiles

// Scratch (fp16)
__device__ __half g_q[B_ * H_ * T_ * HD_];
__device__ __half g_k[B_ * H_ * T_ * HD_];
__device__ __half g_v[B_ * H_ * T_ * HD_];
__device__ __half g_ga[BT_ * D_];                 // GEMM A (x, then attn out)
__device__ __half g_gbhi[D_ * D3_];               // GEMM B hi
__device__ __half g_gblo[D_ * D3_];               // GEMM B lo (W_qkv)

// ============================ PTX helpers ==================================
__device__ __forceinline__ uint32_t smem_u32(const void* p) {
    uint32_t a;
    asm("{ .reg .u64 t; cvta.to.shared.u64 t, %1; cvt.u32.u64 %0, t; }"
        : "=r"(a) : "l"(p));
    return a;
}
#define SWZ(o) ((uint32_t)(o) ^ ((((uint32_t)(o)) >> 3) & 0x70u))

__device__ __forceinline__ void cp16(uint32_t dst, const void* src) {
    asm volatile("cp.async.cg.shared.global [%0], [%1], 16;" :: "r"(dst), "l"(src) : "memory");
}
#define CP_COMMIT() asm volatile("cp.async.commit_group;" ::: "memory")
#define CP_WAIT0()  asm volatile("cp.async.wait_group 0;" ::: "memory")
#define CP_WAIT1()  asm volatile("cp.async.wait_group 1;" ::: "memory")

#define LDSM4(R, a) \
    asm volatile("ldmatrix.sync.aligned.m8n8.x4.shared.b16 {%0,%1,%2,%3}, [%4];" \
        : "=r"((R)[0]), "=r"((R)[1]), "=r"((R)[2]), "=r"((R)[3]) : "r"(a))
#define LDSM4T(R, a) \
    asm volatile("ldmatrix.sync.aligned.m8n8.x4.trans.shared.b16 {%0,%1,%2,%3}, [%4];" \
        : "=r"((R)[0]), "=r"((R)[1]), "=r"((R)[2]), "=r"((R)[3]) : "r"(a))

__device__ __forceinline__ void mma16816h(float* c, const uint32_t* a,
                                          uint32_t b0, uint32_t b1) {
    asm volatile("mma.sync.aligned.m16n8k16.row.col.f32.f16.f16.f32 "
        "{%0,%1,%2,%3}, {%4,%5,%6,%7}, {%8,%9}, {%0,%1,%2,%3};"
        : "+f"(c[0]), "+f"(c[1]), "+f"(c[2]), "+f"(c[3])
        : "r"(a[0]), "r"(a[1]), "r"(a[2]), "r"(a[3]), "r"(b0), "r"(b1));
}

__device__ __forceinline__ uint32_t ex2h2(uint32_t x) {
    uint32_t r;
    asm("ex2.approx.f16x2 %0, %1;" : "=r"(r) : "r"(x));
    return r;
}

__device__ __forceinline__ uint32_t packh2(float x, float y) {
    __half2 h = __floats2half2_rn(x, y);
    return *reinterpret_cast<uint32_t*>(&h);
}

// ===================== elementwise converts ================================
__global__ void tohalf_kernel(const float4* __restrict__ src,
                              uint32_t* __restrict__ dst, int n4) {
    int i = blockIdx.x * blockDim.x + threadIdx.x;
    if (i >= n4) return;
    float4 v = src[i];
    dst[2 * i]     = packh2(v.x, v.y);
    dst[2 * i + 1] = packh2(v.z, v.w);
}
__global__ void split_pair_kernel(const float4* __restrict__ src,
                                  uint32_t* __restrict__ hi,
                                  uint32_t* __restrict__ lo, int n4) {
    int i = blockIdx.x * blockDim.x + threadIdx.x;
    if (i >= n4) return;
    float4 v = src[i];
    __half h0 = __float2half_rn(v.x);
    __half h1 = __float2half_rn(v.y);
    __half h2 = __float2half_rn(v.z);
    __half h3 = __float2half_rn(v.w);
    hi[2 * i]     = (uint32_t)__half_as_ushort(h0)
                  | ((uint32_t)__half_as_ushort(h1) << 16);
    hi[2 * i + 1] = (uint32_t)__half_as_ushort(h2)
                  | ((uint32_t)__half_as_ushort(h3) << 16);
    lo[2 * i]     = packh2(v.x - __half2float(h0), v.y - __half2float(h1));
    lo[2 * i + 1] = packh2(v.z - __half2float(h2), v.w - __half2float(h3));
}

// ============ fp16 tensor-core GEMM: C = A16 * (Bhi [+ Blo]) + bias ========
// BM=256 BN=128 BK=64, 256 thr = 8 warps (4 row x 2 col), warp m64n64.
// PRODS = 1 or 2 (template). mode 0: fp32 C. mode 1: QKV epilogue (RoPE).
constexpr uint32_t GA_   = 0;          // 256 x 64 fp16 = 32KB
constexpr uint32_t GB_HI = 32768;      // 2 halves x (64 x 64 fp16) = 16KB
constexpr uint32_t GB_LO = 49152;
constexpr uint32_t GBUF  = 65536;
constexpr uint32_t GEMM_SMEM = 140288;  // max(2*GBUF, 256*132*4 staging) + pad
constexpr int CSTR = 132;               // staged C tile stride (floats)

template<int PRODS>
__device__ __forceinline__ void gemm_load(
    uint32_t base, int tid, int rowBase, int colBase, int k0, int K, int N,
    const __half* A, const __half* Bhi, const __half* Blo) {
#pragma unroll
    for (int c = tid; c < 2048; c += 256) {          // A: 256 rows x 8 chunks
        int row = c >> 3, off = c & 7;
        uint32_t sw = SWZ(row * 128 + off * 16);
        size_t g = (size_t)(rowBase + row) * K + k0 + off * 8;
        cp16(base + GA_ + sw, A + g);
    }
#pragma unroll
    for (int c = tid; c < 1024; c += 256) {          // B: 2 halves x 64 rows x 8
        int half = c >> 9, cc = c & 511;
        int row = cc >> 3, off = cc & 7;
        uint32_t sw = (uint32_t)(half * 8192) + SWZ(row * 128 + off * 16);
        size_t g = (size_t)(k0 + row) * N + colBase + half * 64 + off * 8;
        cp16(base + GB_HI + sw, Bhi + g);
        if (PRODS == 2) cp16(base + GB_LO + sw, Blo + g);
    }
}

template<int PRODS>
__global__ __launch_bounds__(256, 1)
void gemm_fp16_kernel(const __half* __restrict__ A,
                      const __half* __restrict__ Bhi,
                      const __half* __restrict__ Blo,
                      const float* __restrict__ bias,
                      float* __restrict__ C, int M, int N, int K, int mode) {
    extern __shared__ unsigned char smraw[];
    uint32_t smem = (smem_u32(smraw) + 1023u) & ~1023u;
    unsigned char* smbase = smraw + (smem - smem_u32(smraw));

    const int tid = threadIdx.x;
    const int warp = tid >> 5, lane = tid & 31;
    const int grp = lane >> 3, rIn = lane & 7;
    const int rowBase = blockIdx.y * 256, colBase = blockIdx.x * 128;
    const int wrow = (warp >> 1) * 64;        // 0,64,128,192
    const int halfsel = warp & 1;             // B column half (64 cols)
    const int NIT = K / 64;

    const uint32_t aoff = (uint32_t)((wrow + rIn + (grp & 1) * 8) * 128 + (grp >> 1) * 16);
    const uint32_t boff = (uint32_t)(grp * 1024 + rIn * 128);

    float acc[4][8][4];
#pragma unroll
    for (int m = 0; m < 4; m++)
#pragma unroll
        for (int n = 0; n < 8; n++)
#pragma unroll
            for (int i = 0; i < 4; i++) acc[m][n][i] = 0.0f;

    gemm_load<PRODS>(smem, tid, rowBase, colBase, 0, K, N, A, Bhi, Blo);
    CP_COMMIT();

    for (int it = 0; it < NIT; it++) {
        __syncthreads();
        if (it + 1 < NIT) {
            gemm_load<PRODS>(smem + ((it + 1) & 1) * GBUF, tid, rowBase, colBase,
                             (it + 1) * 64, K, N, A, Bhi, Blo);
            CP_COMMIT();
            CP_WAIT1();
        } else {
            CP_WAIT0();
        }
        __syncthreads();

        const uint32_t base = smem + (uint32_t)(it & 1) * GBUF;
        const uint32_t Ah = base + GA_;
        const uint32_t Bh = base + GB_HI + halfsel * 8192;
        const uint32_t Bl = base + GB_LO + halfsel * 8192;

#pragma unroll
        for (int kh = 0; kh < 2; kh++) {
            uint32_t bh[8][4], bl[8][4];
#pragma unroll
            for (int n = 0; n < 8; n++) {
                uint32_t o = boff + (uint32_t)(kh * 4096 + n * 16);
                LDSM4T(bh[n], Bh + SWZ(o));
                if (PRODS == 2) LDSM4T(bl[n], Bl + SWZ(o));
            }
#pragma unroll
            for (int s = 0; s < 2; s++) {
                uint32_t ah[4][4];
#pragma unroll
                for (int m = 0; m < 4; m++) {
                    uint32_t o = aoff + (uint32_t)(m * 2048 + (kh * 2 + s) * 32);
                    LDSM4(ah[m], Ah + SWZ(o));
                }
#pragma unroll
                for (int m = 0; m < 4; m++)
#pragma unroll
                    for (int n = 0; n < 8; n++) {
                        mma16816h(acc[m][n], ah[m], bh[n][2 * s], bh[n][2 * s + 1]);
                        if (PRODS == 2)
                            mma16816h(acc[m][n], ah[m], bl[n][2 * s], bl[n][2 * s + 1]);
                    }
            }
        }
    }

    const int wc = halfsel * 64;              // warp's 64-col band

    if (mode == 0) {
#pragma unroll
        for (int m = 0; m < 4; m++) {
            int r0 = rowBase + wrow + m * 16 + (lane >> 2);
#pragma unroll
            for (int n = 0; n < 8; n++) {
                int col = colBase + wc + n * 8 + 2 * (lane & 3);
                float bx = bias[col], by = bias[col + 1];
                float2 v0 = make_float2(acc[m][n][0] + bx, acc[m][n][1] + by);
                float2 v1 = make_float2(acc[m][n][2] + bx, acc[m][n][3] + by);
                *reinterpret_cast<float2*>(&C[(size_t)r0 * N + col])       = v0;
                *reinterpret_cast<float2*>(&C[(size_t)(r0 + 8) * N + col]) = v1;
            }
        }
        return;
    }

    // ---- mode 1: QKV epilogue (stage 256x128 tile; RoPE; q,k,v fp16) ----
    __syncthreads();
    float* Csm = reinterpret_cast<float*>(smbase);
#pragma unroll
    for (int m = 0; m < 4; m++) {
        int r0 = wrow + m * 16 + (lane >> 2);
#pragma unroll
        for (int n = 0; n < 8; n++) {
            int col = wc + n * 8 + 2 * (lane & 3);
            float bx = bias[colBase + col], by = bias[colBase + col + 1];
            Csm[r0 * CSTR + col]           = acc[m][n][0] + bx;
            Csm[r0 * CSTR + col + 1]       = acc[m][n][1] + by;
            Csm[(r0 + 8) * CSTR + col]     = acc[m][n][2] + bx;
            Csm[(r0 + 8) * CSTR + col + 1] = acc[m][n][3] + by;
        }
    }
    __syncthreads();

    const int type = colBase >> 10;          // 0=q, 1=k, 2=v
    const int cb2  = colBase & 1023;
    const int h0   = cb2 >> 6;               // first of 2 heads in this tile
    const int bb   = rowBase >> 11;          // batch
    const int t0   = rowBase & 2047;         // first token row

    if (type < 2) {
        __half* dst = (type == 0) ? g_q : g_k;
        int d2 = tid & 63;                   // pair-column within 2 heads
        int lh = d2 >> 5, d = d2 & 31;
        float expo = (float)(2 * d) * (1.0f / (float)HD_);
        float inv  = 1.0f / powf(10000.0f, expo);
        size_t hbase = ((size_t)(bb * H_ + h0 + lh)) * T_ * HD_;
#pragma unroll 4
        for (int rr = tid >> 6; rr < 256; rr += 4) {
            int t = t0 + rr;
            float s, c;
            sincosf((float)t * inv, &s, &c);
            float v1 = Csm[rr * CSTR + lh * 64 + d];
            float v2 = Csm[rr * CSTR + lh * 64 + d + 32];
            size_t o = hbase + (size_t)t * HD_;
            dst[o + d]      = __float2half_rn(v1 * c - v2 * s);
            dst[o + d + 32] = __float2half_rn(v2 * c + v1 * s);
        }
    } else {
        int cc = tid & 127;
        int lh = cc >> 6, d = cc & 63;
        size_t hbase = ((size_t)(bb * H_ + h0 + lh)) * T_ * HD_;
#pragma unroll 4
        for (int rr = tid >> 7; rr < 256; rr += 2) {
            float v = Csm[rr * CSTR + cc];
            g_v[hbase + (size_t)(t0 + rr) * HD_ + d] = __float2half_rn(v);
        }
    }
}

// ================= mma.sync flash attention (pure fp16, R14) ===============
constexpr uint32_t SM_Q  = 0;                      // 16KB
constexpr uint32_t SM_KV = 16384;                  // + buf*32768
constexpr uint32_t KV_K = 0, KV_V = 16384;
constexpr uint32_t SM_BIAS = 16384 + 2 * 32768;    // 81920; T_ floats = 8KB
constexpr uint32_t SMEM_BYTES = 81920 + 8192 + 1024;

constexpr float EXPC = 0.18033688011112042f;       // 0.125 * log2(e)
constexpr uint32_t ONES_H2 = 0x3C003C00u;          // (1.0h, 1.0h)

__device__ __forceinline__ void load_kv_tile(
    uint32_t smem, int buf, int k0, int tid,
    const __half* gk, const __half* gv) {
    uint32_t base = smem + SM_KV + (uint32_t)buf * 32768u;
#pragma unroll
    for (int c = tid; c < 1024; c += 256) {
        int row = c >> 3, off = c & 7;
        uint32_t sw = SWZ(row * 128 + off * 16);
        size_t g = (size_t)(k0 + row) * HD_ + off * 8;
        cp16(base + KV_K + sw, gk + g);
        cp16(base + KV_V + sw, gv + g);
    }
}

__global__ __launch_bounds__(256, 1)
void attn_mma_kernel(const unsigned char* __restrict__ mask) {
    extern __shared__ unsigned char smraw[];
    uint32_t smem = (smem_u32(smraw) + 1023u) & ~1023u;
    unsigned char* smbyte = smraw + (smem - smem_u32(smraw));

    const int tid  = threadIdx.x;
    const int warp = tid >> 5, lane = tid & 31;
    const int grp  = lane >> 3, rIn = lane & 7;
    const int bh = blockIdx.y, b = bh >> 4, h = bh & 15;
    const int q0 = blockIdx.x * 128;
    const int wrow = warp * 16;

    const size_t hb = (size_t)bh * T_ * HD_;
    const __half* gq = g_q + hb + (size_t)q0 * HD_;
    const __half* gk = g_k + hb;
    const __half* gv = g_v + hb;

#pragma unroll
    for (int c = tid; c < 1024; c += 256) {
        int row = c >> 3, off = c & 7;
        uint32_t sw = SWZ(row * 128 + off * 16);
        cp16(smem + SM_Q + sw, gq + (size_t)row * HD_ + off * 8);
    }
    {
        float* biasf = reinterpret_cast<float*>(smbyte + SM_BIAS);
        for (int i = tid; i < T_; i += 256)
            biasf[i] = mask[b * T_ + i] ? -200.0f : 0.0f;
    }
    load_kv_tile(smem, 0, 0, tid, gk, gv);
    CP_COMMIT();
    CP_WAIT0();
    __syncthreads();

    uint32_t qh[4][4];
    const uint32_t qoff = (uint32_t)((wrow + rIn + (grp & 1) * 8) * 128 + (grp >> 1) * 16);
#pragma unroll
    for (int kk = 0; kk < 4; kk++)
        LDSM4(qh[kk], smem + SM_Q + SWZ(qoff + kk * 32));

    float o[8][4];
#pragma unroll
    for (int j = 0; j < 8; j++)
#pragma unroll
        for (int i = 0; i < 4; i++) o[j][i] = 0.0f;
    float ls_acc[4] = {0.0f, 0.0f, 0.0f, 0.0f};

    const uint32_t kb = (uint32_t)(rIn * 128 + grp * 16);
    const uint32_t vb = (uint32_t)(grp * 1024 + rIn * 128);
    const int mcol0 = 2 * (lane & 3);
    const float* biasf = reinterpret_cast<const float*>(smbyte + SM_BIAS);

    for (int t = 0; t < NT_; t++) {
        const uint32_t kvb = smem + SM_KV + (uint32_t)(t & 1) * 32768u;

        __syncthreads();
        if (t + 1 < NT_) {
            load_kv_tile(smem, (t + 1) & 1, (t + 1) * 128, tid, gk, gv);
            CP_COMMIT();
            CP_WAIT1();
        } else {
            CP_WAIT0();
        }
        __syncthreads();

        float c[16][4];
#pragma unroll
        for (int j = 0; j < 16; j++)
#pragma unroll
            for (int i = 0; i < 4; i++) c[j][i] = 0.0f;

#pragma unroll
        for (int kp = 0; kp < 2; kp++) {
#pragma unroll
            for (int j = 0; j < 16; j++) {
                uint32_t kh[4];
                uint32_t off = (uint32_t)(1024 * j + kp * 64) + kb;
                LDSM4(kh, kvb + KV_K + SWZ(off));
                mma16816h(c[j], qh[2 * kp],     kh[0], kh[1]);
                mma16816h(c[j], qh[2 * kp + 1], kh[2], kh[3]);
            }
        }

        const float* bf = biasf + t * 128;
#pragma unroll
        for (int p = 0; p < 4; p++) {
            uint32_t ph[2][4];
#pragma unroll
            for (int q2 = 0; q2 < 2; q2++) {
#pragma unroll
                for (int jj = 0; jj < 2; jj++) {
                    int j = 4 * p + 2 * q2 + jj;
                    int cg = 8 * j + mcol0;
                    float b0 = bf[cg], b1 = bf[cg + 1];
                    float e0 = fmaf(c[j][0], EXPC, b0);
                    float e1 = fmaf(c[j][1], EXPC, b1);
                    float e2 = fmaf(c[j][2], EXPC, b0);
                    float e3 = fmaf(c[j][3], EXPC, b1);
                    ph[q2][2 * jj + 0] = ex2h2(packh2(e0, e1));
                    ph[q2][2 * jj + 1] = ex2h2(packh2(e2, e3));
                }
                mma16816h(ls_acc, ph[q2], ONES_H2, ONES_H2);
            }
#pragma unroll
            for (int jh = 0; jh < 8; jh++) {
                uint32_t vh[4];
                uint32_t off = (uint32_t)(4096 * p + 16 * jh) + vb;
                LDSM4T(vh, kvb + KV_V + SWZ(off));
                mma16816h(o[jh], ph[0], vh[0], vh[1]);
                mma16816h(o[jh], ph[1], vh[2], vh[3]);
            }
        }
    }

    float i0 = 1.0f / ls_acc[0];
    float i1 = 1.0f / ls_acc[2];

    int r = q0 + wrow + (lane >> 2);
    size_t off0 = ((size_t)(b * T_ + r) * D_ + h * HD_ + mcol0) >> 1;  // u32 index
    uint32_t* ga = reinterpret_cast<uint32_t*>(g_ga);
#pragma unroll
    for (int jh = 0; jh < 8; jh++) {
        size_t i_w = off0 + 4 * jh;
        ga[i_w]          = packh2(o[jh][0] * i0, o[jh][1] * i0);
        ga[i_w + 4 * D_] = packh2(o[jh][2] * i1, o[jh][3] * i1);   // row r+8
    }
}

// ============================== Launch =====================================
extern "C" void kernel_launch(void* const* d_in, const int* in_sizes, int n_in,
                              void* d_out, int out_size) {
    const float* x     = (const float*)d_in[0];
    const float* W_qkv = (const float*)d_in[1];
    const float* b_qkv = (const float*)d_in[2];
    const float* W_out = (const float*)d_in[3];
    const float* b_out = (const float*)d_in[4];
    const unsigned char* pmask = (const unsigned char*)d_in[5];
    float* out = (float*)d_out;

    __half *ga, *bhi, *blo;
    cudaGetSymbolAddress((void**)&ga,  g_ga);
    cudaGetSymbolAddress((void**)&bhi, g_gbhi);
    cudaGetSymbolAddress((void**)&blo, g_gblo);

    cudaFuncSetAttribute(gemm_fp16_kernel<2>,
                         cudaFuncAttributeMaxDynamicSharedMemorySize, (int)GEMM_SMEM);
    cudaFuncSetAttribute(gemm_fp16_kernel<1>,
                         cudaFuncAttributeMaxDynamicSharedMemorySize, (int)GEMM_SMEM);
    cudaFuncSetAttribute(attn_mma_kernel,
                         cudaFuncAttributeMaxDynamicSharedMemorySize, (int)SMEM_BYTES);

    // 1) x -> fp16; W_qkv -> fp16 split; fused QKV GEMM (2 prod) + RoPE epilogue
    tohalf_kernel<<<(BT_ * D_ / 4) / 256, 256>>>(
        (const float4*)x, (uint32_t*)ga, BT_ * D_ / 4);
    split_pair_kernel<<<(D_ * D3_ / 4) / 256, 256>>>(
        (const float4*)W_qkv, (uint32_t*)bhi, (uint32_t*)blo, D_ * D3_ / 4);
    gemm_fp16_kernel<2><<<dim3(D3_ / 128, BT_ / 256), 256, GEMM_SMEM>>>(
        ga, bhi, blo, b_qkv, nullptr, BT_, D3_, D_, 1);

    // 2) flash attention (pure fp16; writes out-proj A operand)
    attn_mma_kernel<<<dim3(T_ / 128, B_ * H_), 256, SMEM_BYTES>>>(pmask);

    // 3) W_out -> fp16 (single); out-proj GEMM (1 prod) -> d_out
    tohalf_kernel<<<(D_ * D_ / 4) / 256, 256>>>(
        (const float4*)W_out, (uint32_t*)bhi, D_ * D_ / 4);
    gemm_fp16_kernel<1><<<dim3(D_ / 128, BT_ / 256), 256, GEMM_SMEM>>>(
        ga, bhi, nullptr, b_out, out, BT_, D_, D_, 0);
}

// round 16
// speedup vs baseline: 1.0610x; 1.0065x over previous
#include <cuda_runtime.h>
#include <cuda_fp16.h>
#include <math.h>
#include <stdint.h>

constexpr int B_  = 2;
constexpr int T_  = 2048;
constexpr int D_  = 1024;
constexpr int H_  = 16;
constexpr int HD_ = 64;
constexpr int BT_ = B_ * T_;
constexpr int D3_ = 3 * D_;
constexpr int NT_ = T_ / 128;   // 16 kv tiles

// Scratch (fp16)
__device__ __half g_q[B_ * H_ * T_ * HD_];
__device__ __half g_k[B_ * H_ * T_ * HD_];
__device__ __half g_v[B_ * H_ * T_ * HD_];
__device__ __half g_ga[BT_ * D_];                 // GEMM A (x, then attn out)
__device__ __half g_gbhi[D_ * D3_];               // GEMM B hi
__device__ __half g_gblo[D_ * D3_];               // GEMM B lo (W_qkv)

// ============================ PTX helpers ==================================
__device__ __forceinline__ uint32_t smem_u32(const void* p) {
    uint32_t a;
    asm("{ .reg .u64 t; cvta.to.shared.u64 t, %1; cvt.u32.u64 %0, t; }"
        : "=r"(a) : "l"(p));
    return a;
}
#define SWZ(o) ((uint32_t)(o) ^ ((((uint32_t)(o)) >> 3) & 0x70u))

__device__ __forceinline__ void cp16(uint32_t dst, const void* src) {
    asm volatile("cp.async.cg.shared.global [%0], [%1], 16;" :: "r"(dst), "l"(src) : "memory");
}
#define CP_COMMIT() asm volatile("cp.async.commit_group;" ::: "memory")
#define CP_WAIT0()  asm volatile("cp.async.wait_group 0;" ::: "memory")
#define CP_WAIT1()  asm volatile("cp.async.wait_group 1;" ::: "memory")

#define LDSM4(R, a) \
    asm volatile("ldmatrix.sync.aligned.m8n8.x4.shared.b16 {%0,%1,%2,%3}, [%4];" \
        : "=r"((R)[0]), "=r"((R)[1]), "=r"((R)[2]), "=r"((R)[3]) : "r"(a))
#define LDSM4T(R, a) \
    asm volatile("ldmatrix.sync.aligned.m8n8.x4.trans.shared.b16 {%0,%1,%2,%3}, [%4];" \
        : "=r"((R)[0]), "=r"((R)[1]), "=r"((R)[2]), "=r"((R)[3]) : "r"(a))

__device__ __forceinline__ void mma16816h(float* c, const uint32_t* a,
                                          uint32_t b0, uint32_t b1) {
    asm volatile("mma.sync.aligned.m16n8k16.row.col.f32.f16.f16.f32 "
        "{%0,%1,%2,%3}, {%4,%5,%6,%7}, {%8,%9}, {%0,%1,%2,%3};"
        : "+f"(c[0]), "+f"(c[1]), "+f"(c[2]), "+f"(c[3])
        : "r"(a[0]), "r"(a[1]), "r"(a[2]), "r"(a[3]), "r"(b0), "r"(b1));
}

__device__ __forceinline__ uint32_t ex2h2(uint32_t x) {
    uint32_t r;
    asm("ex2.approx.f16x2 %0, %1;" : "=r"(r) : "r"(x));
    return r;
}

__device__ __forceinline__ uint32_t packh2(float x, float y) {
    __half2 h = __floats2half2_rn(x, y);
    return *reinterpret_cast<uint32_t*>(&h);
}

// ===================== elementwise converts ================================
__global__ void tohalf_kernel(const float4* __restrict__ src,
                              uint32_t* __restrict__ dst, int n4) {
    int i = blockIdx.x * blockDim.x + threadIdx.x;
    if (i >= n4) return;
    float4 v = src[i];
    dst[2 * i]     = packh2(v.x, v.y);
    dst[2 * i + 1] = packh2(v.z, v.w);
}
__global__ void split_pair_kernel(const float4* __restrict__ src,
                                  uint32_t* __restrict__ hi,
                                  uint32_t* __restrict__ lo, int n4) {
    int i = blockIdx.x * blockDim.x + threadIdx.x;
    if (i >= n4) return;
    float4 v = src[i];
    __half h0 = __float2half_rn(v.x);
    __half h1 = __float2half_rn(v.y);
    __half h2 = __float2half_rn(v.z);
    __half h3 = __float2half_rn(v.w);
    hi[2 * i]     = (uint32_t)__half_as_ushort(h0)
                  | ((uint32_t)__half_as_ushort(h1) << 16);
    hi[2 * i + 1] = (uint32_t)__half_as_ushort(h2)
                  | ((uint32_t)__half_as_ushort(h3) << 16);
    lo[2 * i]     = packh2(v.x - __half2float(h0), v.y - __half2float(h1));
    lo[2 * i + 1] = packh2(v.z - __half2float(h2), v.w - __half2float(h3));
}

// ============ fp16 tensor-core GEMM (validated R15): BM=256 BN=128 =========
constexpr uint32_t GA_   = 0;          // 256 x 64 fp16 = 32KB
constexpr uint32_t GB_HI = 32768;
constexpr uint32_t GB_LO = 49152;
constexpr uint32_t GBUF  = 65536;
constexpr uint32_t GEMM_SMEM = 140288;
constexpr int CSTR = 132;

template<int PRODS>
__device__ __forceinline__ void gemm_load(
    uint32_t base, int tid, int rowBase, int colBase, int k0, int K, int N,
    const __half* A, const __half* Bhi, const __half* Blo) {
#pragma unroll
    for (int c = tid; c < 2048; c += 256) {
        int row = c >> 3, off = c & 7;
        uint32_t sw = SWZ(row * 128 + off * 16);
        size_t g = (size_t)(rowBase + row) * K + k0 + off * 8;
        cp16(base + GA_ + sw, A + g);
    }
#pragma unroll
    for (int c = tid; c < 1024; c += 256) {
        int half = c >> 9, cc = c & 511;
        int row = cc >> 3, off = cc & 7;
        uint32_t sw = (uint32_t)(half * 8192) + SWZ(row * 128 + off * 16);
        size_t g = (size_t)(k0 + row) * N + colBase + half * 64 + off * 8;
        cp16(base + GB_HI + sw, Bhi + g);
        if (PRODS == 2) cp16(base + GB_LO + sw, Blo + g);
    }
}

template<int PRODS>
__global__ __launch_bounds__(256, 1)
void gemm_fp16_kernel(const __half* __restrict__ A,
                      const __half* __restrict__ Bhi,
                      const __half* __restrict__ Blo,
                      const float* __restrict__ bias,
                      float* __restrict__ C, int M, int N, int K, int mode) {
    extern __shared__ unsigned char smraw[];
    uint32_t smem = (smem_u32(smraw) + 1023u) & ~1023u;
    unsigned char* smbase = smraw + (smem - smem_u32(smraw));

    const int tid = threadIdx.x;
    const int warp = tid >> 5, lane = tid & 31;
    const int grp = lane >> 3, rIn = lane & 7;
    const int rowBase = blockIdx.y * 256, colBase = blockIdx.x * 128;
    const int wrow = (warp >> 1) * 64;
    const int halfsel = warp & 1;
    const int NIT = K / 64;

    const uint32_t aoff = (uint32_t)((wrow + rIn + (grp & 1) * 8) * 128 + (grp >> 1) * 16);
    const uint32_t boff = (uint32_t)(grp * 1024 + rIn * 128);

    float acc[4][8][4];
#pragma unroll
    for (int m = 0; m < 4; m++)
#pragma unroll
        for (int n = 0; n < 8; n++)
#pragma unroll
            for (int i = 0; i < 4; i++) acc[m][n][i] = 0.0f;

    gemm_load<PRODS>(smem, tid, rowBase, colBase, 0, K, N, A, Bhi, Blo);
    CP_COMMIT();

    for (int it = 0; it < NIT; it++) {
        __syncthreads();
        if (it + 1 < NIT) {
            gemm_load<PRODS>(smem + ((it + 1) & 1) * GBUF, tid, rowBase, colBase,
                             (it + 1) * 64, K, N, A, Bhi, Blo);
            CP_COMMIT();
            CP_WAIT1();
        } else {
            CP_WAIT0();
        }
        __syncthreads();

        const uint32_t base = smem + (uint32_t)(it & 1) * GBUF;
        const uint32_t Ah = base + GA_;
        const uint32_t Bh = base + GB_HI + halfsel * 8192;
        const uint32_t Bl = base + GB_LO + halfsel * 8192;

#pragma unroll
        for (int kh = 0; kh < 2; kh++) {
            uint32_t bh[8][4], bl[8][4];
#pragma unroll
            for (int n = 0; n < 8; n++) {
                uint32_t o = boff + (uint32_t)(kh * 4096 + n * 16);
                LDSM4T(bh[n], Bh + SWZ(o));
                if (PRODS == 2) LDSM4T(bl[n], Bl + SWZ(o));
            }
#pragma unroll
            for (int s = 0; s < 2; s++) {
                uint32_t ah[4][4];
#pragma unroll
                for (int m = 0; m < 4; m++) {
                    uint32_t o = aoff + (uint32_t)(m * 2048 + (kh * 2 + s) * 32);
                    LDSM4(ah[m], Ah + SWZ(o));
                }
#pragma unroll
                for (int m = 0; m < 4; m++)
#pragma unroll
                    for (int n = 0; n < 8; n++) {
                        mma16816h(acc[m][n], ah[m], bh[n][2 * s], bh[n][2 * s + 1]);
                        if (PRODS == 2)
                            mma16816h(acc[m][n], ah[m], bl[n][2 * s], bl[n][2 * s + 1]);
                    }
            }
        }
    }

    const int wc = halfsel * 64;

    if (mode == 0) {
#pragma unroll
        for (int m = 0; m < 4; m++) {
            int r0 = rowBase + wrow + m * 16 + (lane >> 2);
#pragma unroll
            for (int n = 0; n < 8; n++) {
                int col = colBase + wc + n * 8 + 2 * (lane & 3);
                float bx = bias[col], by = bias[col + 1];
                float2 v0 = make_float2(acc[m][n][0] + bx, acc[m][n][1] + by);
                float2 v1 = make_float2(acc[m][n][2] + bx, acc[m][n][3] + by);
                *reinterpret_cast<float2*>(&C[(size_t)r0 * N + col])       = v0;
                *reinterpret_cast<float2*>(&C[(size_t)(r0 + 8) * N + col]) = v1;
            }
        }
        return;
    }

    // ---- mode 1: QKV epilogue (stage 256x128 tile; RoPE; q,k,v fp16) ----
    __syncthreads();
    float* Csm = reinterpret_cast<float*>(smbase);
#pragma unroll
    for (int m = 0; m < 4; m++) {
        int r0 = wrow + m * 16 + (lane >> 2);
#pragma unroll
        for (int n = 0; n < 8; n++) {
            int col = wc + n * 8 + 2 * (lane & 3);
            float bx = bias[colBase + col], by = bias[colBase + col + 1];
            Csm[r0 * CSTR + col]           = acc[m][n][0] + bx;
            Csm[r0 * CSTR + col + 1]       = acc[m][n][1] + by;
            Csm[(r0 + 8) * CSTR + col]     = acc[m][n][2] + bx;
            Csm[(r0 + 8) * CSTR + col + 1] = acc[m][n][3] + by;
        }
    }
    __syncthreads();

    const int type = colBase >> 10;
    const int cb2  = colBase & 1023;
    const int h0   = cb2 >> 6;
    const int bb   = rowBase >> 11;
    const int t0   = rowBase & 2047;

    if (type < 2) {
        __half* dst = (type == 0) ? g_q : g_k;
        int d2 = tid & 63;
        int lh = d2 >> 5, d = d2 & 31;
        float expo = (float)(2 * d) * (1.0f / (float)HD_);
        float inv  = 1.0f / powf(10000.0f, expo);
        size_t hbase = ((size_t)(bb * H_ + h0 + lh)) * T_ * HD_;
#pragma unroll 4
        for (int rr = tid >> 6; rr < 256; rr += 4) {
            int t = t0 + rr;
            float s, c;
            sincosf((float)t * inv, &s, &c);
            float v1 = Csm[rr * CSTR + lh * 64 + d];
            float v2 = Csm[rr * CSTR + lh * 64 + d + 32];
            size_t o = hbase + (size_t)t * HD_;
            dst[o + d]      = __float2half_rn(v1 * c - v2 * s);
            dst[o + d + 32] = __float2half_rn(v2 * c + v1 * s);
        }
    } else {
        int cc = tid & 127;
        int lh = cc >> 6, d = cc & 63;
        size_t hbase = ((size_t)(bb * H_ + h0 + lh)) * T_ * HD_;
#pragma unroll 4
        for (int rr = tid >> 7; rr < 256; rr += 2) {
            float v = Csm[rr * CSTR + cc];
            g_v[hbase + (size_t)(t0 + rr) * HD_ + d] = __float2half_rn(v);
        }
    }
}

// ================= mma.sync flash attention (fp16, 32 q-rows/warp) =========
// CTA: 256 q rows, 8 warps x 32 rows (two m16 tiles each).
// KV processed in two 64-col halves to bound live S accumulators.
constexpr uint32_t SM_Q  = 0;                      // 32KB (256 x 64 fp16)
constexpr uint32_t SM_KV = 32768;                  // + buf*32768
constexpr uint32_t KV_K = 0, KV_V = 16384;
constexpr uint32_t SM_BIAS = 32768 + 2 * 32768;    // 98304; T_ floats = 8KB
constexpr uint32_t SMEM_BYTES = 98304 + 8192 + 1024;

constexpr float EXPC = 0.18033688011112042f;       // 0.125 * log2(e)
constexpr uint32_t ONES_H2 = 0x3C003C00u;

__device__ __forceinline__ void load_kv_tile(
    uint32_t smem, int buf, int k0, int tid,
    const __half* gk, const __half* gv) {
    uint32_t base = smem + SM_KV + (uint32_t)buf * 32768u;
#pragma unroll
    for (int c = tid; c < 1024; c += 256) {
        int row = c >> 3, off = c & 7;
        uint32_t sw = SWZ(row * 128 + off * 16);
        size_t g = (size_t)(k0 + row) * HD_ + off * 8;
        cp16(base + KV_K + sw, gk + g);
        cp16(base + KV_V + sw, gv + g);
    }
}

__global__ __launch_bounds__(256, 1)
void attn_mma_kernel(const unsigned char* __restrict__ mask) {
    extern __shared__ unsigned char smraw[];
    uint32_t smem = (smem_u32(smraw) + 1023u) & ~1023u;
    unsigned char* smbyte = smraw + (smem - smem_u32(smraw));

    const int tid  = threadIdx.x;
    const int warp = tid >> 5, lane = tid & 31;
    const int grp  = lane >> 3, rIn = lane & 7;
    const int bh = blockIdx.y, b = bh >> 4, h = bh & 15;
    const int q0 = blockIdx.x * 256;
    const int wrow = warp * 32;

    const size_t hb = (size_t)bh * T_ * HD_;
    const __half* gq = g_q + hb + (size_t)q0 * HD_;
    const __half* gk = g_k + hb;
    const __half* gv = g_v + hb;

#pragma unroll
    for (int c = tid; c < 2048; c += 256) {
        int row = c >> 3, off = c & 7;
        uint32_t sw = SWZ(row * 128 + off * 16);
        cp16(smem + SM_Q + sw, gq + (size_t)row * HD_ + off * 8);
    }
    {
        float* biasf = reinterpret_cast<float*>(smbyte + SM_BIAS);
        for (int i = tid; i < T_; i += 256)
            biasf[i] = mask[b * T_ + i] ? -200.0f : 0.0f;
    }
    load_kv_tile(smem, 0, 0, tid, gk, gv);
    CP_COMMIT();
    CP_WAIT0();
    __syncthreads();

    // Q fragments for the two m16 tiles
    uint32_t qh[2][4][4];
#pragma unroll
    for (int m = 0; m < 2; m++) {
        uint32_t qoff = (uint32_t)((wrow + m * 16 + rIn + (grp & 1) * 8) * 128
                                   + (grp >> 1) * 16);
#pragma unroll
        for (int kk = 0; kk < 4; kk++)
            LDSM4(qh[m][kk], smem + SM_Q + SWZ(qoff + kk * 32));
    }

    float o[2][8][4];
#pragma unroll
    for (int m = 0; m < 2; m++)
#pragma unroll
        for (int j = 0; j < 8; j++)
#pragma unroll
            for (int i = 0; i < 4; i++) o[m][j][i] = 0.0f;
    float ls_acc[2][4] = {{0.0f, 0.0f, 0.0f, 0.0f}, {0.0f, 0.0f, 0.0f, 0.0f}};

    const uint32_t kb = (uint32_t)(rIn * 128 + grp * 16);
    const uint32_t vb = (uint32_t)(grp * 1024 + rIn * 128);
    const int mcol0 = 2 * (lane & 3);
    const float* biasf = reinterpret_cast<const float*>(smbyte + SM_BIAS);

    for (int t = 0; t < NT_; t++) {
        const uint32_t kvb = smem + SM_KV + (uint32_t)(t & 1) * 32768u;

        __syncthreads();
        if (t + 1 < NT_) {
            load_kv_tile(smem, (t + 1) & 1, (t + 1) * 128, tid, gk, gv);
            CP_COMMIT();
            CP_WAIT1();
        } else {
            CP_WAIT0();
        }
        __syncthreads();

        const float* bf = biasf + t * 128;

#pragma unroll
        for (int hs = 0; hs < 2; hs++) {
            // ---- S for 32 q-rows x 64 kv cols ----
            float c[2][8][4];
#pragma unroll
            for (int m = 0; m < 2; m++)
#pragma unroll
                for (int j = 0; j < 8; j++)
#pragma unroll
                    for (int i = 0; i < 4; i++) c[m][j][i] = 0.0f;

#pragma unroll
            for (int kp = 0; kp < 2; kp++) {
#pragma unroll
                for (int jj = 0; jj < 8; jj++) {
                    int j = hs * 8 + jj;
                    uint32_t kh[4];
                    uint32_t off = (uint32_t)(1024 * j + kp * 64) + kb;
                    LDSM4(kh, kvb + KV_K + SWZ(off));
                    mma16816h(c[0][jj], qh[0][2 * kp],     kh[0], kh[1]);
                    mma16816h(c[0][jj], qh[0][2 * kp + 1], kh[2], kh[3]);
                    mma16816h(c[1][jj], qh[1][2 * kp],     kh[0], kh[1]);
                    mma16816h(c[1][jj], qh[1][2 * kp + 1], kh[2], kh[3]);
                }
            }

            // ---- softmax + PV for this half's two 32-row kv bands ----
#pragma unroll
            for (int pp = 0; pp < 2; pp++) {
                int p = hs * 2 + pp;
                uint32_t ph[2][2][4];   // [m][q2][4]
#pragma unroll
                for (int m = 0; m < 2; m++) {
#pragma unroll
                    for (int q2 = 0; q2 < 2; q2++) {
#pragma unroll
                        for (int jj = 0; jj < 2; jj++) {
                            int jl = 4 * pp + 2 * q2 + jj;
                            int cg = 8 * (hs * 8 + jl) + mcol0;
                            float b0 = bf[cg], b1 = bf[cg + 1];
                            float e0 = fmaf(c[m][jl][0], EXPC, b0);
                            float e1 = fmaf(c[m][jl][1], EXPC, b1);
                            float e2 = fmaf(c[m][jl][2], EXPC, b0);
                            float e3 = fmaf(c[m][jl][3], EXPC, b1);
                            ph[m][q2][2 * jj + 0] = ex2h2(packh2(e0, e1));
                            ph[m][q2][2 * jj + 1] = ex2h2(packh2(e2, e3));
                        }
                        mma16816h(ls_acc[m], ph[m][q2], ONES_H2, ONES_H2);
                    }
                }
#pragma unroll
                for (int jh = 0; jh < 8; jh++) {
                    uint32_t vh[4];
                    uint32_t off = (uint32_t)(4096 * p + 16 * jh) + vb;
                    LDSM4T(vh, kvb + KV_V + SWZ(off));
                    mma16816h(o[0][jh], ph[0][0], vh[0], vh[1]);
                    mma16816h(o[0][jh], ph[0][1], vh[2], vh[3]);
                    mma16816h(o[1][jh], ph[1][0], vh[0], vh[1]);
                    mma16816h(o[1][jh], ph[1][1], vh[2], vh[3]);
                }
            }
        }
    }

    // epilogue: write fp16 O directly into out-proj A operand
    uint32_t* ga = reinterpret_cast<uint32_t*>(g_ga);
#pragma unroll
    for (int m = 0; m < 2; m++) {
        float i0 = 1.0f / ls_acc[m][0];
        float i1 = 1.0f / ls_acc[m][2];
        int r = q0 + wrow + m * 16 + (lane >> 2);
        size_t off0 = ((size_t)(b * T_ + r) * D_ + h * HD_ + mcol0) >> 1;
#pragma unroll
        for (int jh = 0; jh < 8; jh++) {
            size_t i_w = off0 + 4 * jh;
            ga[i_w]          = packh2(o[m][jh][0] * i0, o[m][jh][1] * i0);
            ga[i_w + 4 * D_] = packh2(o[m][jh][2] * i1, o[m][jh][3] * i1);
        }
    }
}

// ============================== Launch =====================================
extern "C" void kernel_launch(void* const* d_in, const int* in_sizes, int n_in,
                              void* d_out, int out_size) {
    const float* x     = (const float*)d_in[0];
    const float* W_qkv = (const float*)d_in[1];
    const float* b_qkv = (const float*)d_in[2];
    const float* W_out = (const float*)d_in[3];
    const float* b_out = (const float*)d_in[4];
    const unsigned char* pmask = (const unsigned char*)d_in[5];
    float* out = (float*)d_out;

    __half *ga, *bhi, *blo;
    cudaGetSymbolAddress((void**)&ga,  g_ga);
    cudaGetSymbolAddress((void**)&bhi, g_gbhi);
    cudaGetSymbolAddress((void**)&blo, g_gblo);

    cudaFuncSetAttribute(gemm_fp16_kernel<2>,
                         cudaFuncAttributeMaxDynamicSharedMemorySize, (int)GEMM_SMEM);
    cudaFuncSetAttribute(gemm_fp16_kernel<1>,
                         cudaFuncAttributeMaxDynamicSharedMemorySize, (int)GEMM_SMEM);
    cudaFuncSetAttribute(attn_mma_kernel,
                         cudaFuncAttributeMaxDynamicSharedMemorySize, (int)SMEM_BYTES);

    // 1) x -> fp16; W_qkv -> fp16 split; fused QKV GEMM (2 prod) + RoPE epilogue
    tohalf_kernel<<<(BT_ * D_ / 4) / 256, 256>>>(
        (const float4*)x, (uint32_t*)ga, BT_ * D_ / 4);
    split_pair_kernel<<<(D_ * D3_ / 4) / 256, 256>>>(
        (const float4*)W_qkv, (uint32_t*)bhi, (uint32_t*)blo, D_ * D3_ / 4);
    gemm_fp16_kernel<2><<<dim3(D3_ / 128, BT_ / 256), 256, GEMM_SMEM>>>(
        ga, bhi, blo, b_qkv, nullptr, BT_, D3_, D_, 1);

    // 2) flash attention (256 q-rows/CTA; writes out-proj A operand)
    attn_mma_kernel<<<dim3(T_ / 256, B_ * H_), 256, SMEM_BYTES>>>(pmask);

    // 3) W_out -> fp16 (single); out-proj GEMM (1 prod) -> d_out
    tohalf_kernel<<<(D_ * D_ / 4) / 256, 256>>>(
        (const float4*)W_out, (uint32_t*)bhi, D_ * D_ / 4);
    gemm_fp16_kernel<1><<<dim3(D_ / 128, BT_ / 256), 256, GEMM_SMEM>>>(
        ga, bhi, nullptr, b_out, out, BT_, D_, D_, 0);
}

// round 17
// speedup vs baseline: 1.0735x; 1.0118x over previous
#include <cuda_runtime.h>
#include <cuda_fp16.h>
#include <math.h>
#include <stdint.h>

constexpr int B_  = 2;
constexpr int T_  = 2048;
constexpr int D_  = 1024;
constexpr int H_  = 16;
constexpr int HD_ = 64;
constexpr int BT_ = B_ * T_;
constexpr int D3_ = 3 * D_;
constexpr int NT_ = T_ / 128;   // 16 kv tiles

// Scratch (fp16)
__device__ __half g_q[B_ * H_ * T_ * HD_];
__device__ __half g_k[B_ * H_ * T_ * HD_];
__device__ __half g_v[B_ * H_ * T_ * HD_];
__device__ __half g_ga[BT_ * D_];                 // GEMM A (x, then attn out)
__device__ __half g_gbhi[D_ * D3_];               // GEMM B hi
__device__ __half g_gblo[D_ * D3_];               // GEMM B lo (W_qkv)

// ============================ PTX helpers ==================================
__device__ __forceinline__ uint32_t smem_u32(const void* p) {
    uint32_t a;
    asm("{ .reg .u64 t; cvta.to.shared.u64 t, %1; cvt.u32.u64 %0, t; }"
        : "=r"(a) : "l"(p));
    return a;
}
#define SWZ(o) ((uint32_t)(o) ^ ((((uint32_t)(o)) >> 3) & 0x70u))

__device__ __forceinline__ void cp16(uint32_t dst, const void* src) {
    asm volatile("cp.async.cg.shared.global [%0], [%1], 16;" :: "r"(dst), "l"(src) : "memory");
}
#define CP_COMMIT() asm volatile("cp.async.commit_group;" ::: "memory")
#define CP_WAIT0()  asm volatile("cp.async.wait_group 0;" ::: "memory")
#define CP_WAIT1()  asm volatile("cp.async.wait_group 1;" ::: "memory")

#define LDSM4(R, a) \
    asm volatile("ldmatrix.sync.aligned.m8n8.x4.shared.b16 {%0,%1,%2,%3}, [%4];" \
        : "=r"((R)[0]), "=r"((R)[1]), "=r"((R)[2]), "=r"((R)[3]) : "r"(a))
#define LDSM4T(R, a) \
    asm volatile("ldmatrix.sync.aligned.m8n8.x4.trans.shared.b16 {%0,%1,%2,%3}, [%4];" \
        : "=r"((R)[0]), "=r"((R)[1]), "=r"((R)[2]), "=r"((R)[3]) : "r"(a))

__device__ __forceinline__ void mma16816h(float* c, const uint32_t* a,
                                          uint32_t b0, uint32_t b1) {
    asm volatile("mma.sync.aligned.m16n8k16.row.col.f32.f16.f16.f32 "
        "{%0,%1,%2,%3}, {%4,%5,%6,%7}, {%8,%9}, {%0,%1,%2,%3};"
        : "+f"(c[0]), "+f"(c[1]), "+f"(c[2]), "+f"(c[3])
        : "r"(a[0]), "r"(a[1]), "r"(a[2]), "r"(a[3]), "r"(b0), "r"(b1));
}

__device__ __forceinline__ uint32_t ex2h2(uint32_t x) {
    uint32_t r;
    asm("ex2.approx.f16x2 %0, %1;" : "=r"(r) : "r"(x));
    return r;
}

__device__ __forceinline__ uint32_t packh2(float x, float y) {
    __half2 h = __floats2half2_rn(x, y);
    return *reinterpret_cast<uint32_t*>(&h);
}

// ===================== elementwise converts ================================
__global__ void tohalf_kernel(const float4* __restrict__ src,
                              uint32_t* __restrict__ dst, int n4) {
    int i = blockIdx.x * blockDim.x + threadIdx.x;
    if (i >= n4) return;
    float4 v = src[i];
    dst[2 * i]     = packh2(v.x, v.y);
    dst[2 * i + 1] = packh2(v.z, v.w);
}
__global__ void split_pair_kernel(const float4* __restrict__ src,
                                  uint32_t* __restrict__ hi,
                                  uint32_t* __restrict__ lo, int n4) {
    int i = blockIdx.x * blockDim.x + threadIdx.x;
    if (i >= n4) return;
    float4 v = src[i];
    __half h0 = __float2half_rn(v.x);
    __half h1 = __float2half_rn(v.y);
    __half h2 = __float2half_rn(v.z);
    __half h3 = __float2half_rn(v.w);
    hi[2 * i]     = (uint32_t)__half_as_ushort(h0)
                  | ((uint32_t)__half_as_ushort(h1) << 16);
    hi[2 * i + 1] = (uint32_t)__half_as_ushort(h2)
                  | ((uint32_t)__half_as_ushort(h3) << 16);
    lo[2 * i]     = packh2(v.x - __half2float(h0), v.y - __half2float(h1));
    lo[2 * i + 1] = packh2(v.z - __half2float(h2), v.w - __half2float(h3));
}

// ============ fp16 tensor-core GEMM (validated R15): BM=256 BN=128 =========
constexpr uint32_t GA_   = 0;          // 256 x 64 fp16 = 32KB
constexpr uint32_t GB_HI = 32768;
constexpr uint32_t GB_LO = 49152;
constexpr uint32_t GBUF  = 65536;
constexpr uint32_t GEMM_SMEM = 140288;
constexpr int CSTR = 132;

template<int PRODS>
__device__ __forceinline__ void gemm_load(
    uint32_t base, int tid, int rowBase, int colBase, int k0, int K, int N,
    const __half* A, const __half* Bhi, const __half* Blo) {
#pragma unroll
    for (int c = tid; c < 2048; c += 256) {
        int row = c >> 3, off = c & 7;
        uint32_t sw = SWZ(row * 128 + off * 16);
        size_t g = (size_t)(rowBase + row) * K + k0 + off * 8;
        cp16(base + GA_ + sw, A + g);
    }
#pragma unroll
    for (int c = tid; c < 1024; c += 256) {
        int half = c >> 9, cc = c & 511;
        int row = cc >> 3, off = cc & 7;
        uint32_t sw = (uint32_t)(half * 8192) + SWZ(row * 128 + off * 16);
        size_t g = (size_t)(k0 + row) * N + colBase + half * 64 + off * 8;
        cp16(base + GB_HI + sw, Bhi + g);
        if (PRODS == 2) cp16(base + GB_LO + sw, Blo + g);
    }
}

template<int PRODS>
__global__ __launch_bounds__(256, 1)
void gemm_fp16_kernel(const __half* __restrict__ A,
                      const __half* __restrict__ Bhi,
                      const __half* __restrict__ Blo,
                      const float* __restrict__ bias,
                      float* __restrict__ C, int M, int N, int K, int mode) {
    extern __shared__ unsigned char smraw[];
    uint32_t smem = (smem_u32(smraw) + 1023u) & ~1023u;
    unsigned char* smbase = smraw + (smem - smem_u32(smraw));

    const int tid = threadIdx.x;
    const int warp = tid >> 5, lane = tid & 31;
    const int grp = lane >> 3, rIn = lane & 7;
    const int rowBase = blockIdx.y * 256, colBase = blockIdx.x * 128;
    const int wrow = (warp >> 1) * 64;
    const int halfsel = warp & 1;
    const int NIT = K / 64;

    const uint32_t aoff = (uint32_t)((wrow + rIn + (grp & 1) * 8) * 128 + (grp >> 1) * 16);
    const uint32_t boff = (uint32_t)(grp * 1024 + rIn * 128);

    float acc[4][8][4];
#pragma unroll
    for (int m = 0; m < 4; m++)
#pragma unroll
        for (int n = 0; n < 8; n++)
#pragma unroll
            for (int i = 0; i < 4; i++) acc[m][n][i] = 0.0f;

    gemm_load<PRODS>(smem, tid, rowBase, colBase, 0, K, N, A, Bhi, Blo);
    CP_COMMIT();

    for (int it = 0; it < NIT; it++) {
        __syncthreads();
        if (it + 1 < NIT) {
            gemm_load<PRODS>(smem + ((it + 1) & 1) * GBUF, tid, rowBase, colBase,
                             (it + 1) * 64, K, N, A, Bhi, Blo);
            CP_COMMIT();
            CP_WAIT1();
        } else {
            CP_WAIT0();
        }
        __syncthreads();

        const uint32_t base = smem + (uint32_t)(it & 1) * GBUF;
        const uint32_t Ah = base + GA_;
        const uint32_t Bh = base + GB_HI + halfsel * 8192;
        const uint32_t Bl = base + GB_LO + halfsel * 8192;

#pragma unroll
        for (int kh = 0; kh < 2; kh++) {
            uint32_t bh[8][4], bl[8][4];
#pragma unroll
            for (int n = 0; n < 8; n++) {
                uint32_t o = boff + (uint32_t)(kh * 4096 + n * 16);
                LDSM4T(bh[n], Bh + SWZ(o));
                if (PRODS == 2) LDSM4T(bl[n], Bl + SWZ(o));
            }
#pragma unroll
            for (int s = 0; s < 2; s++) {
                uint32_t ah[4][4];
#pragma unroll
                for (int m = 0; m < 4; m++) {
                    uint32_t o = aoff + (uint32_t)(m * 2048 + (kh * 2 + s) * 32);
                    LDSM4(ah[m], Ah + SWZ(o));
                }
#pragma unroll
                for (int m = 0; m < 4; m++)
#pragma unroll
                    for (int n = 0; n < 8; n++) {
                        mma16816h(acc[m][n], ah[m], bh[n][2 * s], bh[n][2 * s + 1]);
                        if (PRODS == 2)
                            mma16816h(acc[m][n], ah[m], bl[n][2 * s], bl[n][2 * s + 1]);
                    }
            }
        }
    }

    const int wc = halfsel * 64;

    if (mode == 0) {
#pragma unroll
        for (int m = 0; m < 4; m++) {
            int r0 = rowBase + wrow + m * 16 + (lane >> 2);
#pragma unroll
            for (int n = 0; n < 8; n++) {
                int col = colBase + wc + n * 8 + 2 * (lane & 3);
                float bx = bias[col], by = bias[col + 1];
                float2 v0 = make_float2(acc[m][n][0] + bx, acc[m][n][1] + by);
                float2 v1 = make_float2(acc[m][n][2] + bx, acc[m][n][3] + by);
                *reinterpret_cast<float2*>(&C[(size_t)r0 * N + col])       = v0;
                *reinterpret_cast<float2*>(&C[(size_t)(r0 + 8) * N + col]) = v1;
            }
        }
        return;
    }

    // ---- mode 1: QKV epilogue (stage 256x128 tile; RoPE; q,k,v fp16) ----
    __syncthreads();
    float* Csm = reinterpret_cast<float*>(smbase);
#pragma unroll
    for (int m = 0; m < 4; m++) {
        int r0 = wrow + m * 16 + (lane >> 2);
#pragma unroll
        for (int n = 0; n < 8; n++) {
            int col = wc + n * 8 + 2 * (lane & 3);
            float bx = bias[colBase + col], by = bias[colBase + col + 1];
            Csm[r0 * CSTR + col]           = acc[m][n][0] + bx;
            Csm[r0 * CSTR + col + 1]       = acc[m][n][1] + by;
            Csm[(r0 + 8) * CSTR + col]     = acc[m][n][2] + bx;
            Csm[(r0 + 8) * CSTR + col + 1] = acc[m][n][3] + by;
        }
    }
    __syncthreads();

    const int type = colBase >> 10;
    const int cb2  = colBase & 1023;
    const int h0   = cb2 >> 6;
    const int bb   = rowBase >> 11;
    const int t0   = rowBase & 2047;

    if (type < 2) {
        __half* dst = (type == 0) ? g_q : g_k;
        int d2 = tid & 63;
        int lh = d2 >> 5, d = d2 & 31;
        float expo = (float)(2 * d) * (1.0f / (float)HD_);
        float inv  = 1.0f / powf(10000.0f, expo);
        size_t hbase = ((size_t)(bb * H_ + h0 + lh)) * T_ * HD_;
#pragma unroll 4
        for (int rr = tid >> 6; rr < 256; rr += 4) {
            int t = t0 + rr;
            float s, c;
            sincosf((float)t * inv, &s, &c);
            float v1 = Csm[rr * CSTR + lh * 64 + d];
            float v2 = Csm[rr * CSTR + lh * 64 + d + 32];
            size_t o = hbase + (size_t)t * HD_;
            dst[o + d]      = __float2half_rn(v1 * c - v2 * s);
            dst[o + d + 32] = __float2half_rn(v2 * c + v1 * s);
        }
    } else {
        int cc = tid & 127;
        int lh = cc >> 6, d = cc & 63;
        size_t hbase = ((size_t)(bb * H_ + h0 + lh)) * T_ * HD_;
#pragma unroll 4
        for (int rr = tid >> 7; rr < 256; rr += 2) {
            float v = Csm[rr * CSTR + cc];
            g_v[hbase + (size_t)(t0 + rr) * HD_ + d] = __float2half_rn(v);
        }
    }
}

// ================= mma.sync flash attention (fp16, 32 q-rows/warp) =========
// CTA: 256 q rows, 8 warps x 32 rows. KV in two 64-col halves; even/odd warps
// process halves in OPPOSITE order so the tensor pipe stays busy while the
// other half of the warps run the scalar softmax phase.
constexpr uint32_t SM_Q  = 0;                      // 32KB (256 x 64 fp16)
constexpr uint32_t SM_KV = 32768;                  // + buf*32768
constexpr uint32_t KV_K = 0, KV_V = 16384;
constexpr uint32_t SM_BIAS = 32768 + 2 * 32768;    // 98304; T_ floats = 8KB
constexpr uint32_t SMEM_BYTES = 98304 + 8192 + 1024;

constexpr float EXPC = 0.18033688011112042f;       // 0.125 * log2(e)
constexpr uint32_t ONES_H2 = 0x3C003C00u;

__device__ __forceinline__ void load_kv_tile(
    uint32_t smem, int buf, int k0, int tid,
    const __half* gk, const __half* gv) {
    uint32_t base = smem + SM_KV + (uint32_t)buf * 32768u;
#pragma unroll
    for (int c = tid; c < 1024; c += 256) {
        int row = c >> 3, off = c & 7;
        uint32_t sw = SWZ(row * 128 + off * 16);
        size_t g = (size_t)(k0 + row) * HD_ + off * 8;
        cp16(base + KV_K + sw, gk + g);
        cp16(base + KV_V + sw, gv + g);
    }
}

__global__ __launch_bounds__(256, 1)
void attn_mma_kernel(const unsigned char* __restrict__ mask) {
    extern __shared__ unsigned char smraw[];
    uint32_t smem = (smem_u32(smraw) + 1023u) & ~1023u;
    unsigned char* smbyte = smraw + (smem - smem_u32(smraw));

    const int tid  = threadIdx.x;
    const int warp = tid >> 5, lane = tid & 31;
    const int grp  = lane >> 3, rIn = lane & 7;
    const int bh = blockIdx.y, b = bh >> 4, h = bh & 15;
    const int q0 = blockIdx.x * 256;
    const int wrow = warp * 32;
    const int hs0  = warp & 1;          // phase stagger: odd warps start on hs=1

    const size_t hb = (size_t)bh * T_ * HD_;
    const __half* gq = g_q + hb + (size_t)q0 * HD_;
    const __half* gk = g_k + hb;
    const __half* gv = g_v + hb;

#pragma unroll
    for (int c = tid; c < 2048; c += 256) {
        int row = c >> 3, off = c & 7;
        uint32_t sw = SWZ(row * 128 + off * 16);
        cp16(smem + SM_Q + sw, gq + (size_t)row * HD_ + off * 8);
    }
    {
        float* biasf = reinterpret_cast<float*>(smbyte + SM_BIAS);
        for (int i = tid; i < T_; i += 256)
            biasf[i] = mask[b * T_ + i] ? -200.0f : 0.0f;
    }
    load_kv_tile(smem, 0, 0, tid, gk, gv);
    CP_COMMIT();
    CP_WAIT0();
    __syncthreads();

    uint32_t qh[2][4][4];
#pragma unroll
    for (int m = 0; m < 2; m++) {
        uint32_t qoff = (uint32_t)((wrow + m * 16 + rIn + (grp & 1) * 8) * 128
                                   + (grp >> 1) * 16);
#pragma unroll
        for (int kk = 0; kk < 4; kk++)
            LDSM4(qh[m][kk], smem + SM_Q + SWZ(qoff + kk * 32));
    }

    float o[2][8][4];
#pragma unroll
    for (int m = 0; m < 2; m++)
#pragma unroll
        for (int j = 0; j < 8; j++)
#pragma unroll
            for (int i = 0; i < 4; i++) o[m][j][i] = 0.0f;
    float ls_acc[2][4] = {{0.0f, 0.0f, 0.0f, 0.0f}, {0.0f, 0.0f, 0.0f, 0.0f}};

    const uint32_t kb = (uint32_t)(rIn * 128 + grp * 16);
    const uint32_t vb = (uint32_t)(grp * 1024 + rIn * 128);
    const int mcol0 = 2 * (lane & 3);
    const float* biasf = reinterpret_cast<const float*>(smbyte + SM_BIAS);

    for (int t = 0; t < NT_; t++) {
        const uint32_t kvb = smem + SM_KV + (uint32_t)(t & 1) * 32768u;

        __syncthreads();
        if (t + 1 < NT_) {
            load_kv_tile(smem, (t + 1) & 1, (t + 1) * 128, tid, gk, gv);
            CP_COMMIT();
            CP_WAIT1();
        } else {
            CP_WAIT0();
        }
        __syncthreads();

        const float* bf = biasf + t * 128;

#pragma unroll
        for (int hh = 0; hh < 2; hh++) {
            const int hs = hs0 ^ hh;     // staggered half order per warp parity
            // ---- S for 32 q-rows x 64 kv cols ----
            float c[2][8][4];
#pragma unroll
            for (int m = 0; m < 2; m++)
#pragma unroll
                for (int j = 0; j < 8; j++)
#pragma unroll
                    for (int i = 0; i < 4; i++) c[m][j][i] = 0.0f;

#pragma unroll
            for (int kp = 0; kp < 2; kp++) {
#pragma unroll
                for (int jj = 0; jj < 8; jj++) {
                    int j = hs * 8 + jj;
                    uint32_t kh[4];
                    uint32_t off = (uint32_t)(1024 * j + kp * 64) + kb;
                    LDSM4(kh, kvb + KV_K + SWZ(off));
                    mma16816h(c[0][jj], qh[0][2 * kp],     kh[0], kh[1]);
                    mma16816h(c[0][jj], qh[0][2 * kp + 1], kh[2], kh[3]);
                    mma16816h(c[1][jj], qh[1][2 * kp],     kh[0], kh[1]);
                    mma16816h(c[1][jj], qh[1][2 * kp + 1], kh[2], kh[3]);
                }
            }

            // ---- softmax + PV for this half's two 32-col kv bands ----
#pragma unroll
            for (int pp = 0; pp < 2; pp++) {
                int p = hs * 2 + pp;
                uint32_t ph[2][2][4];   // [m][q2][4]
#pragma unroll
                for (int m = 0; m < 2; m++) {
#pragma unroll
                    for (int q2 = 0; q2 < 2; q2++) {
#pragma unroll
                        for (int jj = 0; jj < 2; jj++) {
                            int jl = 4 * pp + 2 * q2 + jj;
                            int cg = 8 * (hs * 8 + jl) + mcol0;
                            float b0 = bf[cg], b1 = bf[cg + 1];
                            float e0 = fmaf(c[m][jl][0], EXPC, b0);
                            float e1 = fmaf(c[m][jl][1], EXPC, b1);
                            float e2 = fmaf(c[m][jl][2], EXPC, b0);
                            float e3 = fmaf(c[m][jl][3], EXPC, b1);
                            ph[m][q2][2 * jj + 0] = ex2h2(packh2(e0, e1));
                            ph[m][q2][2 * jj + 1] = ex2h2(packh2(e2, e3));
                        }
                        mma16816h(ls_acc[m], ph[m][q2], ONES_H2, ONES_H2);
                    }
                }
#pragma unroll
                for (int jh = 0; jh < 8; jh++) {
                    uint32_t vh[4];
                    uint32_t off = (uint32_t)(4096 * p + 16 * jh) + vb;
                    LDSM4T(vh, kvb + KV_V + SWZ(off));
                    mma16816h(o[0][jh], ph[0][0], vh[0], vh[1]);
                    mma16816h(o[0][jh], ph[0][1], vh[2], vh[3]);
                    mma16816h(o[1][jh], ph[1][0], vh[0], vh[1]);
                    mma16816h(o[1][jh], ph[1][1], vh[2], vh[3]);
                }
            }
        }
    }

    // epilogue: write fp16 O directly into out-proj A operand
    uint32_t* ga = reinterpret_cast<uint32_t*>(g_ga);
#pragma unroll
    for (int m = 0; m < 2; m++) {
        float i0 = 1.0f / ls_acc[m][0];
        float i1 = 1.0f / ls_acc[m][2];
        int r = q0 + wrow + m * 16 + (lane >> 2);
        size_t off0 = ((size_t)(b * T_ + r) * D_ + h * HD_ + mcol0) >> 1;
#pragma unroll
        for (int jh = 0; jh < 8; jh++) {
            size_t i_w = off0 + 4 * jh;
            ga[i_w]          = packh2(o[m][jh][0] * i0, o[m][jh][1] * i0);
            ga[i_w + 4 * D_] = packh2(o[m][jh][2] * i1, o[m][jh][3] * i1);
        }
    }
}

// ============================== Launch =====================================
extern "C" void kernel_launch(void* const* d_in, const int* in_sizes, int n_in,
                              void* d_out, int out_size) {
    const float* x     = (const float*)d_in[0];
    const float* W_qkv = (const float*)d_in[1];
    const float* b_qkv = (const float*)d_in[2];
    const float* W_out = (const float*)d_in[3];
    const float* b_out = (const float*)d_in[4];
    const unsigned char* pmask = (const unsigned char*)d_in[5];
    float* out = (float*)d_out;

    __half *ga, *bhi, *blo;
    cudaGetSymbolAddress((void**)&ga,  g_ga);
    cudaGetSymbolAddress((void**)&bhi, g_gbhi);
    cudaGetSymbolAddress((void**)&blo, g_gblo);

    cudaFuncSetAttribute(gemm_fp16_kernel<2>,
                         cudaFuncAttributeMaxDynamicSharedMemorySize, (int)GEMM_SMEM);
    cudaFuncSetAttribute(gemm_fp16_kernel<1>,
                         cudaFuncAttributeMaxDynamicSharedMemorySize, (int)GEMM_SMEM);
    cudaFuncSetAttribute(attn_mma_kernel,
                         cudaFuncAttributeMaxDynamicSharedMemorySize, (int)SMEM_BYTES);

    // 1) x -> fp16; W_qkv -> fp16 split; fused QKV GEMM (2 prod) + RoPE epilogue
    tohalf_kernel<<<(BT_ * D_ / 4) / 256, 256>>>(
        (const float4*)x, (uint32_t*)ga, BT_ * D_ / 4);
    split_pair_kernel<<<(D_ * D3_ / 4) / 256, 256>>>(
        (const float4*)W_qkv, (uint32_t*)bhi, (uint32_t*)blo, D_ * D3_ / 4);
    gemm_fp16_kernel<2><<<dim3(D3_ / 128, BT_ / 256), 256, GEMM_SMEM>>>(
        ga, bhi, blo, b_qkv, nullptr, BT_, D3_, D_, 1);

    // 2) flash attention (256 q-rows/CTA; phase-staggered warps)
    attn_mma_kernel<<<dim3(T_ / 256, B_ * H_), 256, SMEM_BYTES>>>(pmask);

    // 3) W_out -> fp16 (single); out-proj GEMM (1 prod) -> d_out
    tohalf_kernel<<<(D_ * D_ / 4) / 256, 256>>>(
        (const float4*)W_out, (uint32_t*)bhi, D_ * D_ / 4);
    gemm_fp16_kernel<1><<<dim3(D_ / 128, BT_ / 256), 256, GEMM_SMEM>>>(
        ga, bhi, nullptr, b_out, out, BT_, D_, D_, 0);
}